// round 9
// baseline (speedup 1.0000x reference)
#include <cuda_runtime.h>
#include <cuda_fp16.h>
#include <cstdint>

#define HEADS 16
#define CDIM  512
#define NTOK  64
#define BWIN  2048
#define NWIN  256
#define MROWS (BWIN * NTOK)        // 131072

// ---------------- static scratch ----------------
__device__ __half g_qkv_h[(size_t)MROWS * 3 * CDIM];    // qkv in half
__device__ __half g_att_h[(size_t)MROWS * CDIM];        // attn out in half
__device__ __half g_wqkv_h[3 * CDIM * CDIM];
__device__ __half g_wproj_h[CDIM * CDIM];
__device__ float  g_rpb[HEADS * NTOK * NTOK];
__device__ float  g_cmb[(size_t)NWIN * HEADS * NTOK * NTOK];  // rpb+mask combined (64MB)
__device__ float  g_qkvb[3 * CDIM];

// ---------------- helpers ----------------
__device__ __forceinline__ uint32_t s2u(const void* p) {
    uint32_t a;
    asm("{ .reg .u64 t; cvta.to.shared.u64 t, %1; cvt.u32.u64 %0, t; }" : "=r"(a) : "l"(p));
    return a;
}
__device__ __forceinline__ void cpa16(uint32_t dst, const void* src) {
    asm volatile("cp.async.cg.shared.global [%0], [%1], 16;" :: "r"(dst), "l"(src) : "memory");
}
__device__ __forceinline__ void ldsm4(uint32_t r[4], uint32_t a) {
    asm volatile("ldmatrix.sync.aligned.m8n8.x4.shared.b16 {%0,%1,%2,%3}, [%4];"
                 : "=r"(r[0]), "=r"(r[1]), "=r"(r[2]), "=r"(r[3]) : "r"(a));
}
__device__ __forceinline__ void ldsm4t(uint32_t r[4], uint32_t a) {
    asm volatile("ldmatrix.sync.aligned.m8n8.x4.trans.shared.b16 {%0,%1,%2,%3}, [%4];"
                 : "=r"(r[0]), "=r"(r[1]), "=r"(r[2]), "=r"(r[3]) : "r"(a));
}
__device__ __forceinline__ void mma_f16(float c[4], const uint32_t a[4],
                                        uint32_t b0, uint32_t b1) {
    asm volatile(
        "mma.sync.aligned.m16n8k16.row.col.f32.f16.f16.f32 "
        "{%0,%1,%2,%3}, {%4,%5,%6,%7}, {%8,%9}, {%0,%1,%2,%3};"
        : "+f"(c[0]), "+f"(c[1]), "+f"(c[2]), "+f"(c[3])
        : "r"(a[0]), "r"(a[1]), "r"(a[2]), "r"(a[3]), "r"(b0), "r"(b1));
}
__device__ __forceinline__ uint32_t pack_h2(float a, float b) {
    half2 h = __floats2half2_rn(a, b);
    return *reinterpret_cast<uint32_t*>(&h);
}

// ---------------- fp32 -> fp16 conversion (weights only) ----------------
__global__ void cvt_kernel(const float* __restrict__ src, __half* __restrict__ dst, int n4) {
    int i = blockIdx.x * 256 + threadIdx.x;
    if (i < n4) {
        float4 v = ((const float4*)src)[i];
        ((half2*)dst)[2 * i]     = __floats2half2_rn(v.x, v.y);
        ((half2*)dst)[2 * i + 1] = __floats2half2_rn(v.z, v.w);
    }
}

// ---------------- prep: rpb gather + fused qkv bias ----------------
__global__ void prep_kernel(const float* __restrict__ q_bias,
                            const float* __restrict__ v_bias,
                            const float* __restrict__ rpb_table,
                            const int*   __restrict__ rel_index) {
    int idx = blockIdx.x * 256 + threadIdx.x;
    if (idx < 3 * CDIM) {
        float v = 0.f;
        if (idx < CDIM)           v = q_bias[idx];
        else if (idx >= 2 * CDIM) v = v_bias[idx - 2 * CDIM];
        g_qkvb[idx] = v;
    }
    if (idx < HEADS * NTOK * NTOK) {
        int h  = idx >> 12;
        int nm = idx & 4095;
        g_rpb[idx] = rpb_table[rel_index[nm] * HEADS + h];
    }
}

// ---------------- prep2: combined bias table cmb[w][h] = rpb[h] + mask[w] ----
__global__ void prep2_kernel(const float* __restrict__ mask) {
    int i = blockIdx.x * 256 + threadIdx.x;      // float4 index
    int nm4 = i & 1023;          // (64*64/4)
    int wh  = i >> 10;
    int h = wh & (HEADS - 1), w = wh >> 4;
    float4 rb = ((const float4*)g_rpb)[(h << 10) + nm4];
    float4 mk = ((const float4*)mask)[((size_t)w << 10) + nm4];
    float4 o;
    o.x = rb.x + mk.x; o.y = rb.y + mk.y; o.z = rb.z + mk.z; o.w = rb.w + mk.w;
    ((float4*)g_cmb)[i] = o;
}

// ---------------- GEMM common tile constants (R6-proven) ----------------
#define BK      64
#define ROW_B   144                 // bytes per smem row (64 halves + 8 pad)
#define STG_A   (128 * ROW_B)       // 18432
#define STG     (2 * STG_A)         // 36864
#define NSTG    3
#define GEMM_SMEM (NSTG * STG)      // 110592

// ---------------- QKV GEMM with fused A-conversion (fp32 x -> half smem) ----
// C[M,1536] = X[M,512](fp32) * Wqkv[1536,512]^T + bias. 256 thr, 8 warps
// (4M x 2N, 32x64 warp tiles), 3-stage: B via cp.async, A via LDG+cvt+STS
// staged one full iteration ahead.
__global__ __launch_bounds__(256, 2)
void qkv_gemm(const float* __restrict__ X, const __half* __restrict__ Bw,
              const float* __restrict__ bias, __half* __restrict__ Cout) {
    extern __shared__ __align__(16) char smem[];
    const uint32_t sb = s2u(smem);
    const int tid = threadIdx.x, lane = tid & 31, warp = tid >> 5;
    const int wm = warp & 3, wn = warp >> 2;     // 4M x 2N warp grid
    const int m0 = blockIdx.y * 128, n0 = blockIdx.x * 128;

    const int arow = tid >> 1;                   // 0..127
    const int acol = (tid & 1) * 32;             // float col within 64-block
    const float* Xp = X + (size_t)(m0 + arow) * CDIM + acol;
    const __half* Bg = Bw + (size_t)n0 * CDIM;

    uint4 hA[4];                                 // 32 halves staged in regs

#define LDGCVT(kb) do { \
    const float4* xp_ = (const float4*)(Xp + (kb) * 64); \
    float4 t0 = xp_[0], t1 = xp_[1], t2 = xp_[2], t3 = xp_[3]; \
    float4 t4 = xp_[4], t5 = xp_[5], t6 = xp_[6], t7 = xp_[7]; \
    hA[0] = make_uint4(pack_h2(t0.x,t0.y), pack_h2(t0.z,t0.w), pack_h2(t1.x,t1.y), pack_h2(t1.z,t1.w)); \
    hA[1] = make_uint4(pack_h2(t2.x,t2.y), pack_h2(t2.z,t2.w), pack_h2(t3.x,t3.y), pack_h2(t3.z,t3.w)); \
    hA[2] = make_uint4(pack_h2(t4.x,t4.y), pack_h2(t4.z,t4.w), pack_h2(t5.x,t5.y), pack_h2(t5.z,t5.w)); \
    hA[3] = make_uint4(pack_h2(t6.x,t6.y), pack_h2(t6.z,t6.w), pack_h2(t7.x,t7.y), pack_h2(t7.z,t7.w)); \
} while (0)

#define STSA(kb) do { \
    char* ap_ = smem + ((kb) % NSTG) * STG + arow * ROW_B + acol * 2; \
    ((uint4*)ap_)[0] = hA[0]; ((uint4*)ap_)[1] = hA[1]; \
    ((uint4*)ap_)[2] = hA[2]; ((uint4*)ap_)[3] = hA[3]; \
} while (0)

#define CPAB(kb) do { \
    uint32_t db_ = sb + ((kb) % NSTG) * STG + STG_A; \
    const __half* gb_ = Bg + (kb) * BK; \
    _Pragma("unroll") \
    for (int i_ = 0; i_ < 4; i_++) { \
        int f_ = tid + 256 * i_; int r_ = f_ >> 3; int cc_ = f_ & 7; \
        cpa16(db_ + r_ * ROW_B + cc_ * 16, gb_ + (size_t)r_ * CDIM + cc_ * 8); \
    } \
    asm volatile("cp.async.commit_group;" ::: "memory"); \
} while (0)

    LDGCVT(0); STSA(0); LDGCVT(1);
    CPAB(0); CPAB(1);

    float c[2][8][4];
#pragma unroll
    for (int mt = 0; mt < 2; mt++)
#pragma unroll
        for (int nt = 0; nt < 8; nt++)
#pragma unroll
            for (int r = 0; r < 4; r++) c[mt][nt][r] = 0.f;

    const uint32_t aoff = (wm * 32 + (lane & 15)) * ROW_B + (lane >> 4) * 16;
    const uint32_t boff = STG_A + (wn * 64 + (lane & 7) + ((lane >> 4) & 1) * 8) * ROW_B
                          + ((lane >> 3) & 1) * 16;

    for (int kb = 0; kb < 8; kb++) {
        if (kb < 6) asm volatile("cp.async.wait_group 1;" ::: "memory");
        else        asm volatile("cp.async.wait_group 0;" ::: "memory");
        __syncthreads();
        if (kb + 2 < 8) CPAB(kb + 2);

        uint32_t ab = sb + (kb % NSTG) * STG + aoff;
        uint32_t bb = sb + (kb % NSTG) * STG + boff;
#pragma unroll
        for (int ks = 0; ks < 4; ks++) {
            uint32_t a[2][4], b[4][4];
#pragma unroll
            for (int mt = 0; mt < 2; mt++) ldsm4(a[mt], ab + mt * 16 * ROW_B + ks * 32);
#pragma unroll
            for (int jt = 0; jt < 4; jt++) ldsm4(b[jt], bb + jt * 16 * ROW_B + ks * 32);
#pragma unroll
            for (int mt = 0; mt < 2; mt++)
#pragma unroll
                for (int nt = 0; nt < 8; nt++)
                    mma_f16(c[mt][nt], a[mt], b[nt >> 1][(nt & 1) * 2], b[nt >> 1][(nt & 1) * 2 + 1]);
        }

        if (kb + 1 < 8) {
            STSA(kb + 1);                     // stage freed at kb-2; sync(kb) guards
            if (kb + 2 < 8) LDGCVT(kb + 2);   // full iteration of latency cover
        }
    }

    // epilogue: half2 stores with bias
#pragma unroll
    for (int nt = 0; nt < 8; nt++) {
        int col = n0 + wn * 64 + nt * 8 + (lane & 3) * 2;
        float2 bv = *(const float2*)(bias + col);
#pragma unroll
        for (int mt = 0; mt < 2; mt++) {
            int r = m0 + wm * 32 + mt * 16 + (lane >> 2);
            *(half2*)(Cout + (size_t)r * (3 * CDIM) + col) =
                __floats2half2_rn(c[mt][nt][0] + bv.x, c[mt][nt][1] + bv.y);
            *(half2*)(Cout + (size_t)(r + 8) * (3 * CDIM) + col) =
                __floats2half2_rn(c[mt][nt][2] + bv.x, c[mt][nt][3] + bv.y);
        }
    }
#undef LDGCVT
#undef STSA
#undef CPAB
}

// ---------------- proj GEMM (R6 8-warp config): C = A*B^T + bias, fp32 out ----
__global__ __launch_bounds__(256, 2)
void gemm_proj(const __half* __restrict__ A, const __half* __restrict__ B,
               const float* __restrict__ bias, float* __restrict__ Cout,
               int N, int K) {
    extern __shared__ __align__(16) char smem[];
    const uint32_t sb = s2u(smem);
    const int tid = threadIdx.x, lane = tid & 31, warp = tid >> 5;
    const int wm = warp & 3, wn = warp >> 2;
    const int m0 = blockIdx.y * 128, n0 = blockIdx.x * 128;

    const __half* Ag = A + (size_t)m0 * K;
    const __half* Bg = B + (size_t)n0 * K;

    float c[2][8][4];
#pragma unroll
    for (int mt = 0; mt < 2; mt++)
#pragma unroll
        for (int nt = 0; nt < 8; nt++)
#pragma unroll
            for (int r = 0; r < 4; r++) c[mt][nt][r] = 0.f;

#define LOAD_STAGE(s, kb) do { \
    _Pragma("unroll") \
    for (int i = 0; i < 4; i++) { \
        int f = tid + 256 * i; \
        int row = f >> 3; int cc = f & 7; \
        cpa16(sb + (s) * STG + row * ROW_B + cc * 16, \
              Ag + (size_t)(kb) * BK + (size_t)row * K + cc * 8); \
        cpa16(sb + (s) * STG + STG_A + row * ROW_B + cc * 16, \
              Bg + (size_t)(kb) * BK + (size_t)row * K + cc * 8); \
    } \
    asm volatile("cp.async.commit_group;" ::: "memory"); \
} while (0)

    LOAD_STAGE(0, 0);
    LOAD_STAGE(1, 1);

    const uint32_t aoff = (wm * 32 + (lane & 15)) * ROW_B + (lane >> 4) * 16;
    const uint32_t boff = STG_A + (wn * 64 + (lane & 7) + ((lane >> 4) & 1) * 8) * ROW_B
                          + ((lane >> 3) & 1) * 16;
    const int KB = K / BK;   // 8

    for (int kb = 0; kb < KB; kb++) {
        if (kb + 2 < KB) asm volatile("cp.async.wait_group 1;" ::: "memory");
        else             asm volatile("cp.async.wait_group 0;" ::: "memory");
        __syncthreads();
        if (kb + 2 < KB) { int s = (kb + 2) % NSTG; LOAD_STAGE(s, kb + 2); }

        uint32_t ab = sb + (kb % NSTG) * STG + aoff;
        uint32_t bb = sb + (kb % NSTG) * STG + boff;
#pragma unroll
        for (int ks = 0; ks < 4; ks++) {
            uint32_t a[2][4], b[4][4];
#pragma unroll
            for (int mt = 0; mt < 2; mt++) ldsm4(a[mt], ab + mt * 16 * ROW_B + ks * 32);
#pragma unroll
            for (int jt = 0; jt < 4; jt++) ldsm4(b[jt], bb + jt * 16 * ROW_B + ks * 32);
#pragma unroll
            for (int mt = 0; mt < 2; mt++)
#pragma unroll
                for (int nt = 0; nt < 8; nt++)
                    mma_f16(c[mt][nt], a[mt], b[nt >> 1][(nt & 1) * 2], b[nt >> 1][(nt & 1) * 2 + 1]);
        }
    }

#pragma unroll
    for (int nt = 0; nt < 8; nt++) {
        int col = n0 + wn * 64 + nt * 8 + (lane & 3) * 2;
        float2 bv = *(const float2*)(bias + col);
#pragma unroll
        for (int mt = 0; mt < 2; mt++) {
            int r = m0 + wm * 32 + mt * 16 + (lane >> 2);
            *(float2*)(Cout + (size_t)r * N + col) =
                make_float2(c[mt][nt][0] + bv.x, c[mt][nt][1] + bv.y);
            *(float2*)(Cout + (size_t)(r + 8) * N + col) =
                make_float2(c[mt][nt][2] + bv.x, c[mt][nt][3] + bv.y);
        }
    }
#undef LOAD_STAGE
}

// ---------------- fused window attention (R6 config: direct cmb loads) ------
__global__ __launch_bounds__(128)
void attn_kernel() {
    __shared__ __align__(16) __half q_s[64][40];
    __shared__ __align__(16) __half k_s[64][40];
    __shared__ __align__(16) __half v_s[64][40];

    const int tid = threadIdx.x, lane = tid & 31, warp = tid >> 5;
    const int h = blockIdx.x, b = blockIdx.y, w = b & (NWIN - 1);

    const __half* base = g_qkv_h + (size_t)b * NTOK * 3 * CDIM + h * 32;

    {
        int rr = tid >> 1, hc = (tid & 1) * 16;
        const __half* gp = base + (size_t)rr * (3 * CDIM);
        *(uint4*)&q_s[rr][hc]     = *(const uint4*)(gp + hc);
        *(uint4*)&q_s[rr][hc + 8] = *(const uint4*)(gp + hc + 8);
        *(uint4*)&k_s[rr][hc]     = *(const uint4*)(gp + CDIM + hc);
        *(uint4*)&k_s[rr][hc + 8] = *(const uint4*)(gp + CDIM + hc + 8);
        *(uint4*)&v_s[rr][hc]     = *(const uint4*)(gp + 2 * CDIM + hc);
        *(uint4*)&v_s[rr][hc + 8] = *(const uint4*)(gp + 2 * CDIM + hc + 8);
    }
    __syncthreads();

    float sc[8][4];
#pragma unroll
    for (int nt = 0; nt < 8; nt++)
#pragma unroll
        for (int r = 0; r < 4; r++) sc[nt][r] = 0.f;

    uint32_t qa = s2u(q_s) + (warp * 16 + (lane & 15)) * 80 + (lane >> 4) * 16;
    uint32_t ka = s2u(k_s) + ((lane & 7) + ((lane >> 4) & 1) * 8) * 80 + ((lane >> 3) & 1) * 16;
#pragma unroll
    for (int ks = 0; ks < 2; ks++) {
        uint32_t aq[4];
        ldsm4(aq, qa + ks * 32);
        uint32_t bk[4][4];
#pragma unroll
        for (int jt = 0; jt < 4; jt++) ldsm4(bk[jt], ka + jt * 16 * 80 + ks * 32);
#pragma unroll
        for (int nt = 0; nt < 8; nt++)
            mma_f16(sc[nt], aq, bk[nt >> 1][(nt & 1) * 2], bk[nt >> 1][(nt & 1) * 2 + 1]);
    }

    const float scale = 0.17677669529663687f;   // 32^-0.5
    const int r = warp * 16 + (lane >> 2);
    {
        const float* cmb = g_cmb + ((size_t)(w * HEADS + h) << 12);
#pragma unroll
        for (int nt = 0; nt < 8; nt++) {
            int col = nt * 8 + (lane & 3) * 2;
            float2 c0 = *(const float2*)(cmb + r * 64 + col);
            sc[nt][0] = fmaf(sc[nt][0], scale, c0.x);
            sc[nt][1] = fmaf(sc[nt][1], scale, c0.y);
            float2 c1 = *(const float2*)(cmb + (r + 8) * 64 + col);
            sc[nt][2] = fmaf(sc[nt][2], scale, c1.x);
            sc[nt][3] = fmaf(sc[nt][3], scale, c1.y);
        }
    }

    float mx0 = -1e30f, mx1 = -1e30f;
#pragma unroll
    for (int nt = 0; nt < 8; nt++) {
        mx0 = fmaxf(mx0, fmaxf(sc[nt][0], sc[nt][1]));
        mx1 = fmaxf(mx1, fmaxf(sc[nt][2], sc[nt][3]));
    }
    mx0 = fmaxf(mx0, __shfl_xor_sync(0xffffffff, mx0, 1));
    mx0 = fmaxf(mx0, __shfl_xor_sync(0xffffffff, mx0, 2));
    mx1 = fmaxf(mx1, __shfl_xor_sync(0xffffffff, mx1, 1));
    mx1 = fmaxf(mx1, __shfl_xor_sync(0xffffffff, mx1, 2));

    float s0 = 0.f, s1 = 0.f;
#pragma unroll
    for (int nt = 0; nt < 8; nt++) {
        sc[nt][0] = __expf(sc[nt][0] - mx0);
        sc[nt][1] = __expf(sc[nt][1] - mx0);
        s0 += sc[nt][0] + sc[nt][1];
        sc[nt][2] = __expf(sc[nt][2] - mx1);
        sc[nt][3] = __expf(sc[nt][3] - mx1);
        s1 += sc[nt][2] + sc[nt][3];
    }
    s0 += __shfl_xor_sync(0xffffffff, s0, 1);
    s0 += __shfl_xor_sync(0xffffffff, s0, 2);
    s1 += __shfl_xor_sync(0xffffffff, s1, 1);
    s1 += __shfl_xor_sync(0xffffffff, s1, 2);
    const float inv0 = 1.f / s0, inv1 = 1.f / s1;

    float oc[4][4];
#pragma unroll
    for (int nt = 0; nt < 4; nt++)
#pragma unroll
        for (int rr = 0; rr < 4; rr++) oc[nt][rr] = 0.f;

    uint32_t va = s2u(v_s) + ((lane & 7) + ((lane >> 3) & 1) * 8) * 80 + ((lane >> 4) & 1) * 16;
#pragma unroll
    for (int ks = 0; ks < 4; ks++) {
        uint32_t ap[4];
        ap[0] = pack_h2(sc[2 * ks][0],     sc[2 * ks][1]);
        ap[1] = pack_h2(sc[2 * ks][2],     sc[2 * ks][3]);
        ap[2] = pack_h2(sc[2 * ks + 1][0], sc[2 * ks + 1][1]);
        ap[3] = pack_h2(sc[2 * ks + 1][2], sc[2 * ks + 1][3]);
        uint32_t bv[2][4];
        ldsm4t(bv[0], va + ks * 16 * 80);
        ldsm4t(bv[1], va + ks * 16 * 80 + 32);
#pragma unroll
        for (int nt = 0; nt < 4; nt++)
            mma_f16(oc[nt], ap, bv[nt >> 1][(nt & 1) * 2], bv[nt >> 1][(nt & 1) * 2 + 1]);
    }

    __half* op = g_att_h + (size_t)b * NTOK * CDIM + h * 32;
#pragma unroll
    for (int nt = 0; nt < 4; nt++) {
        int d = nt * 8 + (lane & 3) * 2;
        *(half2*)(op + (size_t)r * CDIM + d) =
            __floats2half2_rn(oc[nt][0] * inv0, oc[nt][1] * inv0);
        *(half2*)(op + (size_t)(r + 8) * CDIM + d) =
            __floats2half2_rn(oc[nt][2] * inv1, oc[nt][3] * inv1);
    }
}

// ---------------- launcher ----------------
extern "C" void kernel_launch(void* const* d_in, const int* in_sizes, int n_in,
                              void* d_out, int out_size) {
    const float* x         = (const float*)d_in[0];
    const float* mask      = (const float*)d_in[1];
    const float* qkv_w     = (const float*)d_in[2];
    const float* q_bias    = (const float*)d_in[3];
    const float* v_bias    = (const float*)d_in[4];
    const float* rpb_table = (const float*)d_in[5];
    const float* proj_w    = (const float*)d_in[6];
    const float* proj_b    = (const float*)d_in[7];
    const int*   rel_index = (const int*)d_in[8];
    float* out = (float*)d_out;

    void *p_qkvh, *p_atth, *p_wqkv, *p_wproj, *p_qkvb;
    cudaGetSymbolAddress(&p_qkvh,  g_qkv_h);
    cudaGetSymbolAddress(&p_atth,  g_att_h);
    cudaGetSymbolAddress(&p_wqkv,  g_wqkv_h);
    cudaGetSymbolAddress(&p_wproj, g_wproj_h);
    cudaGetSymbolAddress(&p_qkvb,  g_qkvb);

    cudaFuncSetAttribute(qkv_gemm,  cudaFuncAttributeMaxDynamicSharedMemorySize, GEMM_SMEM);
    cudaFuncSetAttribute(gemm_proj, cudaFuncAttributeMaxDynamicSharedMemorySize, GEMM_SMEM);

    // launch idx 0: qkv weights -> half
    cvt_kernel<<<(3 * CDIM * CDIM / 4 + 255) / 256, 256>>>(qkv_w, (__half*)p_wqkv, 3 * CDIM * CDIM / 4);
    // idx 1: proj weights -> half (needed much later; placed here for profiling order)
    cvt_kernel<<<(CDIM * CDIM / 4 + 255) / 256, 256>>>(proj_w, (__half*)p_wproj, CDIM * CDIM / 4);
    // idx 2: rpb gather + fused qkv bias
    prep_kernel<<<256, 256>>>(q_bias, v_bias, rpb_table, rel_index);

    // idx 3 (ncu capture slot): fused QKV GEMM, x converted in-kernel
    qkv_gemm<<<dim3(1536 / 128, MROWS / 128), 256, GEMM_SMEM>>>(
        x, (const __half*)p_wqkv, (const float*)p_qkvb, (__half*)p_qkvh);

    // idx 4: combined bias table (needs g_rpb; must precede attn)
    prep2_kernel<<<(NWIN * HEADS * 4096 / 4) / 256, 256>>>(mask);

    // idx 5: fused window attention -> g_att_h
    attn_kernel<<<dim3(HEADS, BWIN), 128>>>();

    // idx 6: proj GEMM -> out (fp32)
    gemm_proj<<<dim3(CDIM / 128, MROWS / 128), 256, GEMM_SMEM>>>(
        (const __half*)p_atth, (const __half*)p_wproj, proj_b,
        out, CDIM, CDIM);
}

// round 10
// speedup vs baseline: 1.4953x; 1.4953x over previous
#include <cuda_runtime.h>
#include <cuda_fp16.h>
#include <cstdint>

#define HEADS 16
#define CDIM  512
#define NTOK  64
#define BWIN  2048
#define NWIN  256
#define MROWS (BWIN * NTOK)        // 131072

// ---------------- static scratch ----------------
__device__ __half g_x_h[(size_t)MROWS * CDIM];          // x in half
__device__ __half g_qkv_h[(size_t)MROWS * 3 * CDIM];    // qkv in half
__device__ __half g_att_h[(size_t)MROWS * CDIM];        // attn out in half
__device__ __half g_wqkv_h[3 * CDIM * CDIM];
__device__ __half g_wproj_h[CDIM * CDIM];
__device__ float  g_rpb[HEADS * NTOK * NTOK];
__device__ float  g_cmb[(size_t)NWIN * HEADS * NTOK * NTOK];  // rpb+mask combined (64MB)
__device__ float  g_qkvb[3 * CDIM];

// ---------------- helpers ----------------
__device__ __forceinline__ uint32_t s2u(const void* p) {
    uint32_t a;
    asm("{ .reg .u64 t; cvta.to.shared.u64 t, %1; cvt.u32.u64 %0, t; }" : "=r"(a) : "l"(p));
    return a;
}
__device__ __forceinline__ void cpa16(uint32_t dst, const void* src) {
    asm volatile("cp.async.cg.shared.global [%0], [%1], 16;" :: "r"(dst), "l"(src) : "memory");
}
__device__ __forceinline__ void ldsm4(uint32_t r[4], uint32_t a) {
    asm volatile("ldmatrix.sync.aligned.m8n8.x4.shared.b16 {%0,%1,%2,%3}, [%4];"
                 : "=r"(r[0]), "=r"(r[1]), "=r"(r[2]), "=r"(r[3]) : "r"(a));
}
__device__ __forceinline__ void ldsm4t(uint32_t r[4], uint32_t a) {
    asm volatile("ldmatrix.sync.aligned.m8n8.x4.trans.shared.b16 {%0,%1,%2,%3}, [%4];"
                 : "=r"(r[0]), "=r"(r[1]), "=r"(r[2]), "=r"(r[3]) : "r"(a));
}
__device__ __forceinline__ void mma_f16(float c[4], const uint32_t a[4],
                                        uint32_t b0, uint32_t b1) {
    asm volatile(
        "mma.sync.aligned.m16n8k16.row.col.f32.f16.f16.f32 "
        "{%0,%1,%2,%3}, {%4,%5,%6,%7}, {%8,%9}, {%0,%1,%2,%3};"
        : "+f"(c[0]), "+f"(c[1]), "+f"(c[2]), "+f"(c[3])
        : "r"(a[0]), "r"(a[1]), "r"(a[2]), "r"(a[3]), "r"(b0), "r"(b1));
}
__device__ __forceinline__ uint32_t pack_h2(float a, float b) {
    half2 h = __floats2half2_rn(a, b);
    return *reinterpret_cast<uint32_t*>(&h);
}

// ---------------- prep: rpb gather + fused qkv bias ----------------
__global__ void prep_kernel(const float* __restrict__ q_bias,
                            const float* __restrict__ v_bias,
                            const float* __restrict__ rpb_table,
                            const int*   __restrict__ rel_index) {
    int idx = blockIdx.x * 256 + threadIdx.x;
    if (idx < 3 * CDIM) {
        float v = 0.f;
        if (idx < CDIM)           v = q_bias[idx];
        else if (idx >= 2 * CDIM) v = v_bias[idx - 2 * CDIM];
        g_qkvb[idx] = v;
    }
    if (idx < HEADS * NTOK * NTOK) {
        int h  = idx >> 12;
        int nm = idx & 4095;
        g_rpb[idx] = rpb_table[rel_index[nm] * HEADS + h];
    }
}

// ---------------- big_prep: cvt x -> half, cmb table, cvt qkv_w -> half ----
// (all independent given prep_kernel completed)
#define XB   65536        // blocks for x cvt (16777216 float4 / 256)
#define PB   16384        // blocks for prep2 (4194304 float4 / 256)
#define WB   768          // blocks for wqkv cvt (196608 float4 / 256)
__global__ void big_prep(const float* __restrict__ x,
                         const float* __restrict__ mask,
                         const float* __restrict__ qkv_w) {
    int bid = blockIdx.x;
    if (bid < XB) {
        int i = bid * 256 + threadIdx.x;
        float4 v = ((const float4*)x)[i];
        ((half2*)g_x_h)[2 * i]     = __floats2half2_rn(v.x, v.y);
        ((half2*)g_x_h)[2 * i + 1] = __floats2half2_rn(v.z, v.w);
    } else if (bid < XB + PB) {
        int i = (bid - XB) * 256 + threadIdx.x;      // float4 index
        int nm4 = i & 1023;
        int wh  = i >> 10;
        int h = wh & (HEADS - 1), w = wh >> 4;
        float4 rb = ((const float4*)g_rpb)[(h << 10) + nm4];
        float4 mk = ((const float4*)mask)[((size_t)w << 10) + nm4];
        float4 o;
        o.x = rb.x + mk.x; o.y = rb.y + mk.y; o.z = rb.z + mk.z; o.w = rb.w + mk.w;
        ((float4*)g_cmb)[i] = o;
    } else {
        int i = (bid - XB - PB) * 256 + threadIdx.x;
        float4 v = ((const float4*)qkv_w)[i];
        ((half2*)g_wqkv_h)[2 * i]     = __floats2half2_rn(v.x, v.y);
        ((half2*)g_wqkv_h)[2 * i + 1] = __floats2half2_rn(v.z, v.w);
    }
}

// ---------------- plain weight cvt (proj) ----------------
__global__ void cvt_kernel(const float* __restrict__ src, __half* __restrict__ dst, int n4) {
    int i = blockIdx.x * 256 + threadIdx.x;
    if (i < n4) {
        float4 v = ((const float4*)src)[i];
        ((half2*)dst)[2 * i]     = __floats2half2_rn(v.x, v.y);
        ((half2*)dst)[2 * i + 1] = __floats2half2_rn(v.z, v.w);
    }
}

// ---------------- fp16 GEMM (R6 8-warp): C = A*B^T + bias ----------------
#define BK      64
#define ROW_B   144
#define STG_A   (128 * ROW_B)
#define STG     (2 * STG_A)
#define NSTG    3
#define GEMM_SMEM (NSTG * STG)      // 110592

template<bool HOUT>
__global__ __launch_bounds__(256, 2)
void gemm_h(const __half* __restrict__ A, const __half* __restrict__ B,
            const float* __restrict__ bias, void* __restrict__ Cout,
            int N, int K) {
    extern __shared__ __align__(16) char smem[];
    const uint32_t sb = s2u(smem);
    const int tid = threadIdx.x, lane = tid & 31, warp = tid >> 5;
    const int wm = warp & 3, wn = warp >> 2;
    const int m0 = blockIdx.y * 128, n0 = blockIdx.x * 128;

    const __half* Ag = A + (size_t)m0 * K;
    const __half* Bg = B + (size_t)n0 * K;

    float c[2][8][4];
#pragma unroll
    for (int mt = 0; mt < 2; mt++)
#pragma unroll
        for (int nt = 0; nt < 8; nt++)
#pragma unroll
            for (int r = 0; r < 4; r++) c[mt][nt][r] = 0.f;

#define LOAD_STAGE(s, kb) do { \
    _Pragma("unroll") \
    for (int i = 0; i < 4; i++) { \
        int f = tid + 256 * i; \
        int row = f >> 3; int cc = f & 7; \
        cpa16(sb + (s) * STG + row * ROW_B + cc * 16, \
              Ag + (size_t)(kb) * BK + (size_t)row * K + cc * 8); \
        cpa16(sb + (s) * STG + STG_A + row * ROW_B + cc * 16, \
              Bg + (size_t)(kb) * BK + (size_t)row * K + cc * 8); \
    } \
    asm volatile("cp.async.commit_group;" ::: "memory"); \
} while (0)

    LOAD_STAGE(0, 0);
    LOAD_STAGE(1, 1);

    const uint32_t aoff = (wm * 32 + (lane & 15)) * ROW_B + (lane >> 4) * 16;
    const uint32_t boff = STG_A + (wn * 64 + (lane & 7) + ((lane >> 4) & 1) * 8) * ROW_B
                          + ((lane >> 3) & 1) * 16;
    const int KB = K / BK;   // 8

    for (int kb = 0; kb < KB; kb++) {
        if (kb + 2 < KB) asm volatile("cp.async.wait_group 1;" ::: "memory");
        else             asm volatile("cp.async.wait_group 0;" ::: "memory");
        __syncthreads();
        if (kb + 2 < KB) { int s = (kb + 2) % NSTG; LOAD_STAGE(s, kb + 2); }

        uint32_t ab = sb + (kb % NSTG) * STG + aoff;
        uint32_t bb = sb + (kb % NSTG) * STG + boff;
#pragma unroll
        for (int ks = 0; ks < 4; ks++) {
            uint32_t a[2][4], b[4][4];
#pragma unroll
            for (int mt = 0; mt < 2; mt++) ldsm4(a[mt], ab + mt * 16 * ROW_B + ks * 32);
#pragma unroll
            for (int jt = 0; jt < 4; jt++) ldsm4(b[jt], bb + jt * 16 * ROW_B + ks * 32);
#pragma unroll
            for (int mt = 0; mt < 2; mt++)
#pragma unroll
                for (int nt = 0; nt < 8; nt++)
                    mma_f16(c[mt][nt], a[mt], b[nt >> 1][(nt & 1) * 2], b[nt >> 1][(nt & 1) * 2 + 1]);
        }
    }

#pragma unroll
    for (int nt = 0; nt < 8; nt++) {
        int col = n0 + wn * 64 + nt * 8 + (lane & 3) * 2;
        float2 bv = *(const float2*)(bias + col);
        if (HOUT) {
            __half* Cp = (__half*)Cout;
#pragma unroll
            for (int mt = 0; mt < 2; mt++) {
                int r = m0 + wm * 32 + mt * 16 + (lane >> 2);
                *(half2*)(Cp + (size_t)r * N + col) =
                    __floats2half2_rn(c[mt][nt][0] + bv.x, c[mt][nt][1] + bv.y);
                *(half2*)(Cp + (size_t)(r + 8) * N + col) =
                    __floats2half2_rn(c[mt][nt][2] + bv.x, c[mt][nt][3] + bv.y);
            }
        } else {
            float* Cp = (float*)Cout;
#pragma unroll
            for (int mt = 0; mt < 2; mt++) {
                int r = m0 + wm * 32 + mt * 16 + (lane >> 2);
                *(float2*)(Cp + (size_t)r * N + col) =
                    make_float2(c[mt][nt][0] + bv.x, c[mt][nt][1] + bv.y);
                *(float2*)(Cp + (size_t)(r + 8) * N + col) =
                    make_float2(c[mt][nt][2] + bv.x, c[mt][nt][3] + bv.y);
            }
        }
    }
#undef LOAD_STAGE
}

// ---------------- fused window attention (R6 config: direct cmb loads) ------
__global__ __launch_bounds__(128)
void attn_kernel() {
    __shared__ __align__(16) __half q_s[64][40];
    __shared__ __align__(16) __half k_s[64][40];
    __shared__ __align__(16) __half v_s[64][40];

    const int tid = threadIdx.x, lane = tid & 31, warp = tid >> 5;
    const int h = blockIdx.x, b = blockIdx.y, w = b & (NWIN - 1);

    const __half* base = g_qkv_h + (size_t)b * NTOK * 3 * CDIM + h * 32;

    {
        int rr = tid >> 1, hc = (tid & 1) * 16;
        const __half* gp = base + (size_t)rr * (3 * CDIM);
        *(uint4*)&q_s[rr][hc]     = *(const uint4*)(gp + hc);
        *(uint4*)&q_s[rr][hc + 8] = *(const uint4*)(gp + hc + 8);
        *(uint4*)&k_s[rr][hc]     = *(const uint4*)(gp + CDIM + hc);
        *(uint4*)&k_s[rr][hc + 8] = *(const uint4*)(gp + CDIM + hc + 8);
        *(uint4*)&v_s[rr][hc]     = *(const uint4*)(gp + 2 * CDIM + hc);
        *(uint4*)&v_s[rr][hc + 8] = *(const uint4*)(gp + 2 * CDIM + hc + 8);
    }
    __syncthreads();

    float sc[8][4];
#pragma unroll
    for (int nt = 0; nt < 8; nt++)
#pragma unroll
        for (int r = 0; r < 4; r++) sc[nt][r] = 0.f;

    uint32_t qa = s2u(q_s) + (warp * 16 + (lane & 15)) * 80 + (lane >> 4) * 16;
    uint32_t ka = s2u(k_s) + ((lane & 7) + ((lane >> 4) & 1) * 8) * 80 + ((lane >> 3) & 1) * 16;
#pragma unroll
    for (int ks = 0; ks < 2; ks++) {
        uint32_t aq[4];
        ldsm4(aq, qa + ks * 32);
        uint32_t bk[4][4];
#pragma unroll
        for (int jt = 0; jt < 4; jt++) ldsm4(bk[jt], ka + jt * 16 * 80 + ks * 32);
#pragma unroll
        for (int nt = 0; nt < 8; nt++)
            mma_f16(sc[nt], aq, bk[nt >> 1][(nt & 1) * 2], bk[nt >> 1][(nt & 1) * 2 + 1]);
    }

    const float scale = 0.17677669529663687f;   // 32^-0.5
    const int r = warp * 16 + (lane >> 2);
    {
        const float* cmb = g_cmb + ((size_t)(w * HEADS + h) << 12);
#pragma unroll
        for (int nt = 0; nt < 8; nt++) {
            int col = nt * 8 + (lane & 3) * 2;
            float2 c0 = *(const float2*)(cmb + r * 64 + col);
            sc[nt][0] = fmaf(sc[nt][0], scale, c0.x);
            sc[nt][1] = fmaf(sc[nt][1], scale, c0.y);
            float2 c1 = *(const float2*)(cmb + (r + 8) * 64 + col);
            sc[nt][2] = fmaf(sc[nt][2], scale, c1.x);
            sc[nt][3] = fmaf(sc[nt][3], scale, c1.y);
        }
    }

    float mx0 = -1e30f, mx1 = -1e30f;
#pragma unroll
    for (int nt = 0; nt < 8; nt++) {
        mx0 = fmaxf(mx0, fmaxf(sc[nt][0], sc[nt][1]));
        mx1 = fmaxf(mx1, fmaxf(sc[nt][2], sc[nt][3]));
    }
    mx0 = fmaxf(mx0, __shfl_xor_sync(0xffffffff, mx0, 1));
    mx0 = fmaxf(mx0, __shfl_xor_sync(0xffffffff, mx0, 2));
    mx1 = fmaxf(mx1, __shfl_xor_sync(0xffffffff, mx1, 1));
    mx1 = fmaxf(mx1, __shfl_xor_sync(0xffffffff, mx1, 2));

    float s0 = 0.f, s1 = 0.f;
#pragma unroll
    for (int nt = 0; nt < 8; nt++) {
        sc[nt][0] = __expf(sc[nt][0] - mx0);
        sc[nt][1] = __expf(sc[nt][1] - mx0);
        s0 += sc[nt][0] + sc[nt][1];
        sc[nt][2] = __expf(sc[nt][2] - mx1);
        sc[nt][3] = __expf(sc[nt][3] - mx1);
        s1 += sc[nt][2] + sc[nt][3];
    }
    s0 += __shfl_xor_sync(0xffffffff, s0, 1);
    s0 += __shfl_xor_sync(0xffffffff, s0, 2);
    s1 += __shfl_xor_sync(0xffffffff, s1, 1);
    s1 += __shfl_xor_sync(0xffffffff, s1, 2);
    const float inv0 = 1.f / s0, inv1 = 1.f / s1;

    float oc[4][4];
#pragma unroll
    for (int nt = 0; nt < 4; nt++)
#pragma unroll
        for (int rr = 0; rr < 4; rr++) oc[nt][rr] = 0.f;

    uint32_t va = s2u(v_s) + ((lane & 7) + ((lane >> 3) & 1) * 8) * 80 + ((lane >> 4) & 1) * 16;
#pragma unroll
    for (int ks = 0; ks < 4; ks++) {
        uint32_t ap[4];
        ap[0] = pack_h2(sc[2 * ks][0],     sc[2 * ks][1]);
        ap[1] = pack_h2(sc[2 * ks][2],     sc[2 * ks][3]);
        ap[2] = pack_h2(sc[2 * ks + 1][0], sc[2 * ks + 1][1]);
        ap[3] = pack_h2(sc[2 * ks + 1][2], sc[2 * ks + 1][3]);
        uint32_t bv[2][4];
        ldsm4t(bv[0], va + ks * 16 * 80);
        ldsm4t(bv[1], va + ks * 16 * 80 + 32);
#pragma unroll
        for (int nt = 0; nt < 4; nt++)
            mma_f16(oc[nt], ap, bv[nt >> 1][(nt & 1) * 2], bv[nt >> 1][(nt & 1) * 2 + 1]);
    }

    __half* op = g_att_h + (size_t)b * NTOK * CDIM + h * 32;
#pragma unroll
    for (int nt = 0; nt < 4; nt++) {
        int d = nt * 8 + (lane & 3) * 2;
        *(half2*)(op + (size_t)r * CDIM + d) =
            __floats2half2_rn(oc[nt][0] * inv0, oc[nt][1] * inv0);
        *(half2*)(op + (size_t)(r + 8) * CDIM + d) =
            __floats2half2_rn(oc[nt][2] * inv1, oc[nt][3] * inv1);
    }
}

// ---------------- launcher ----------------
extern "C" void kernel_launch(void* const* d_in, const int* in_sizes, int n_in,
                              void* d_out, int out_size) {
    const float* x         = (const float*)d_in[0];
    const float* mask      = (const float*)d_in[1];
    const float* qkv_w     = (const float*)d_in[2];
    const float* q_bias    = (const float*)d_in[3];
    const float* v_bias    = (const float*)d_in[4];
    const float* rpb_table = (const float*)d_in[5];
    const float* proj_w    = (const float*)d_in[6];
    const float* proj_b    = (const float*)d_in[7];
    const int*   rel_index = (const int*)d_in[8];
    float* out = (float*)d_out;

    void *p_xh, *p_qkvh, *p_atth, *p_wqkv, *p_wproj, *p_qkvb;
    cudaGetSymbolAddress(&p_xh,    g_x_h);
    cudaGetSymbolAddress(&p_qkvh,  g_qkv_h);
    cudaGetSymbolAddress(&p_atth,  g_att_h);
    cudaGetSymbolAddress(&p_wqkv,  g_wqkv_h);
    cudaGetSymbolAddress(&p_wproj, g_wproj_h);
    cudaGetSymbolAddress(&p_qkvb,  g_qkvb);

    cudaFuncSetAttribute(gemm_h<true>,  cudaFuncAttributeMaxDynamicSharedMemorySize, GEMM_SMEM);
    cudaFuncSetAttribute(gemm_h<false>, cudaFuncAttributeMaxDynamicSharedMemorySize, GEMM_SMEM);

    // idx 0: rpb gather + fused qkv bias
    prep_kernel<<<256, 256>>>(q_bias, v_bias, rpb_table, rel_index);

    // idx 1: fused cvt_x + cmb table + cvt_wqkv (independent, after prep)
    big_prep<<<XB + PB + WB, 256>>>(x, mask, qkv_w);

    // idx 2: QKV GEMM -> g_qkv_h
    gemm_h<true><<<dim3(1536 / 128, MROWS / 128), 256, GEMM_SMEM>>>(
        (const __half*)p_xh, (const __half*)p_wqkv, (const float*)p_qkvb,
        p_qkvh, 3 * CDIM, CDIM);

    // idx 3 (ncu capture slot): fused window attention -> g_att_h
    attn_kernel<<<dim3(HEADS, BWIN), 128>>>();

    // idx 4: proj weights -> half
    cvt_kernel<<<(CDIM * CDIM / 4 + 255) / 256, 256>>>(proj_w, (__half*)p_wproj, CDIM * CDIM / 4);

    // idx 5: proj GEMM -> out (fp32)
    gemm_h<false><<<dim3(CDIM / 128, MROWS / 128), 256, GEMM_SMEM>>>(
        (const __half*)p_atth, (const __half*)p_wproj, proj_b,
        out, CDIM, CDIM);
}

// round 11
// speedup vs baseline: 1.5033x; 1.0053x over previous
#include <cuda_runtime.h>
#include <cuda_fp16.h>
#include <cstdint>

#define HEADS 16
#define CDIM  512
#define NTOK  64
#define BWIN  2048
#define NWIN  256
#define MROWS (BWIN * NTOK)        // 131072

// ---------------- static scratch ----------------
__device__ __half g_x_h[(size_t)MROWS * CDIM];          // x in half
__device__ __half g_qkv_h[(size_t)MROWS * 3 * CDIM];    // qkv in half
__device__ __half g_att_h[(size_t)MROWS * CDIM];        // attn out in half
__device__ __half g_wqkv_h[3 * CDIM * CDIM];
__device__ __half g_wproj_h[CDIM * CDIM];
__device__ float  g_rpb[HEADS * NTOK * NTOK];
__device__ __half g_cmb_h[(size_t)NWIN * HEADS * NTOK * NTOK];  // rpb+mask, half (32MB)
__device__ float  g_qkvb[3 * CDIM];

// ---------------- helpers ----------------
__device__ __forceinline__ uint32_t s2u(const void* p) {
    uint32_t a;
    asm("{ .reg .u64 t; cvta.to.shared.u64 t, %1; cvt.u32.u64 %0, t; }" : "=r"(a) : "l"(p));
    return a;
}
__device__ __forceinline__ void cpa16(uint32_t dst, const void* src) {
    asm volatile("cp.async.cg.shared.global [%0], [%1], 16;" :: "r"(dst), "l"(src) : "memory");
}
__device__ __forceinline__ void ldsm4(uint32_t r[4], uint32_t a) {
    asm volatile("ldmatrix.sync.aligned.m8n8.x4.shared.b16 {%0,%1,%2,%3}, [%4];"
                 : "=r"(r[0]), "=r"(r[1]), "=r"(r[2]), "=r"(r[3]) : "r"(a));
}
__device__ __forceinline__ void ldsm4t(uint32_t r[4], uint32_t a) {
    asm volatile("ldmatrix.sync.aligned.m8n8.x4.trans.shared.b16 {%0,%1,%2,%3}, [%4];"
                 : "=r"(r[0]), "=r"(r[1]), "=r"(r[2]), "=r"(r[3]) : "r"(a));
}
__device__ __forceinline__ void mma_f16(float c[4], const uint32_t a[4],
                                        uint32_t b0, uint32_t b1) {
    asm volatile(
        "mma.sync.aligned.m16n8k16.row.col.f32.f16.f16.f32 "
        "{%0,%1,%2,%3}, {%4,%5,%6,%7}, {%8,%9}, {%0,%1,%2,%3};"
        : "+f"(c[0]), "+f"(c[1]), "+f"(c[2]), "+f"(c[3])
        : "r"(a[0]), "r"(a[1]), "r"(a[2]), "r"(a[3]), "r"(b0), "r"(b1));
}
__device__ __forceinline__ uint32_t pack_h2(float a, float b) {
    half2 h = __floats2half2_rn(a, b);
    return *reinterpret_cast<uint32_t*>(&h);
}

// ---------------- prep A: fused qkv bias ----------------
__global__ void prep_bias(const float* __restrict__ q_bias,
                          const float* __restrict__ v_bias) {
    int idx = blockIdx.x * 256 + threadIdx.x;   // grid 6 x 256 = 1536
    float v = 0.f;
    if (idx < CDIM)           v = q_bias[idx];
    else if (idx >= 2 * CDIM) v = v_bias[idx - 2 * CDIM];
    g_qkvb[idx] = v;
}

// ---------------- prep B: rpb gather ----------------
__global__ void prep_rpb(const float* __restrict__ rpb_table,
                         const int*   __restrict__ rel_index) {
    int idx = blockIdx.x * 256 + threadIdx.x;   // grid 256 -> 65536
    int h  = idx >> 12;
    int nm = idx & 4095;
    g_rpb[idx] = rpb_table[rel_index[nm] * HEADS + h];
}

// ---------------- big_prep: cvt x, cmb(half), cvt wqkv, cvt wproj ----------
#define XB   65536        // x cvt       (16777216 float4 / 256)
#define PB   16384        // cmb         (4194304 float4 / 256)
#define WB   768          // wqkv cvt    (196608 float4 / 256)
#define WB2  256          // wproj cvt   (65536 float4 / 256)
__global__ void big_prep(const float* __restrict__ x,
                         const float* __restrict__ mask,
                         const float* __restrict__ qkv_w,
                         const float* __restrict__ proj_w) {
    int bid = blockIdx.x;
    if (bid < XB) {
        int i = bid * 256 + threadIdx.x;
        float4 v = ((const float4*)x)[i];
        ((half2*)g_x_h)[2 * i]     = __floats2half2_rn(v.x, v.y);
        ((half2*)g_x_h)[2 * i + 1] = __floats2half2_rn(v.z, v.w);
    } else if (bid < XB + PB) {
        int i = (bid - XB) * 256 + threadIdx.x;      // float4 index
        int nm4 = i & 1023;
        int wh  = i >> 10;
        int h = wh & (HEADS - 1), w = wh >> 4;
        float4 rb = ((const float4*)g_rpb)[(h << 10) + nm4];
        float4 mk = ((const float4*)mask)[((size_t)w << 10) + nm4];
        ((half2*)g_cmb_h)[2 * i]     = __floats2half2_rn(rb.x + mk.x, rb.y + mk.y);
        ((half2*)g_cmb_h)[2 * i + 1] = __floats2half2_rn(rb.z + mk.z, rb.w + mk.w);
    } else if (bid < XB + PB + WB) {
        int i = (bid - XB - PB) * 256 + threadIdx.x;
        float4 v = ((const float4*)qkv_w)[i];
        ((half2*)g_wqkv_h)[2 * i]     = __floats2half2_rn(v.x, v.y);
        ((half2*)g_wqkv_h)[2 * i + 1] = __floats2half2_rn(v.z, v.w);
    } else {
        int i = (bid - XB - PB - WB) * 256 + threadIdx.x;
        float4 v = ((const float4*)proj_w)[i];
        ((half2*)g_wproj_h)[2 * i]     = __floats2half2_rn(v.x, v.y);
        ((half2*)g_wproj_h)[2 * i + 1] = __floats2half2_rn(v.z, v.w);
    }
}

// ---------------- fp16 GEMM (R6 8-warp): C = A*B^T + bias ----------------
#define BK      64
#define ROW_B   144
#define STG_A   (128 * ROW_B)
#define STG     (2 * STG_A)
#define NSTG    3
#define GEMM_SMEM (NSTG * STG)      // 110592

template<bool HOUT>
__global__ __launch_bounds__(256, 2)
void gemm_h(const __half* __restrict__ A, const __half* __restrict__ B,
            const float* __restrict__ bias, void* __restrict__ Cout,
            int N, int K) {
    extern __shared__ __align__(16) char smem[];
    const uint32_t sb = s2u(smem);
    const int tid = threadIdx.x, lane = tid & 31, warp = tid >> 5;
    const int wm = warp & 3, wn = warp >> 2;
    const int m0 = blockIdx.y * 128, n0 = blockIdx.x * 128;

    const __half* Ag = A + (size_t)m0 * K;
    const __half* Bg = B + (size_t)n0 * K;

    float c[2][8][4];
#pragma unroll
    for (int mt = 0; mt < 2; mt++)
#pragma unroll
        for (int nt = 0; nt < 8; nt++)
#pragma unroll
            for (int r = 0; r < 4; r++) c[mt][nt][r] = 0.f;

#define LOAD_STAGE(s, kb) do { \
    _Pragma("unroll") \
    for (int i = 0; i < 4; i++) { \
        int f = tid + 256 * i; \
        int row = f >> 3; int cc = f & 7; \
        cpa16(sb + (s) * STG + row * ROW_B + cc * 16, \
              Ag + (size_t)(kb) * BK + (size_t)row * K + cc * 8); \
        cpa16(sb + (s) * STG + STG_A + row * ROW_B + cc * 16, \
              Bg + (size_t)(kb) * BK + (size_t)row * K + cc * 8); \
    } \
    asm volatile("cp.async.commit_group;" ::: "memory"); \
} while (0)

    LOAD_STAGE(0, 0);
    LOAD_STAGE(1, 1);

    const uint32_t aoff = (wm * 32 + (lane & 15)) * ROW_B + (lane >> 4) * 16;
    const uint32_t boff = STG_A + (wn * 64 + (lane & 7) + ((lane >> 4) & 1) * 8) * ROW_B
                          + ((lane >> 3) & 1) * 16;
    const int KB = K / BK;   // 8

    for (int kb = 0; kb < KB; kb++) {
        if (kb + 2 < KB) asm volatile("cp.async.wait_group 1;" ::: "memory");
        else             asm volatile("cp.async.wait_group 0;" ::: "memory");
        __syncthreads();
        if (kb + 2 < KB) { int s = (kb + 2) % NSTG; LOAD_STAGE(s, kb + 2); }

        uint32_t ab = sb + (kb % NSTG) * STG + aoff;
        uint32_t bb = sb + (kb % NSTG) * STG + boff;
#pragma unroll
        for (int ks = 0; ks < 4; ks++) {
            uint32_t a[2][4], b[4][4];
#pragma unroll
            for (int mt = 0; mt < 2; mt++) ldsm4(a[mt], ab + mt * 16 * ROW_B + ks * 32);
#pragma unroll
            for (int jt = 0; jt < 4; jt++) ldsm4(b[jt], bb + jt * 16 * ROW_B + ks * 32);
#pragma unroll
            for (int mt = 0; mt < 2; mt++)
#pragma unroll
                for (int nt = 0; nt < 8; nt++)
                    mma_f16(c[mt][nt], a[mt], b[nt >> 1][(nt & 1) * 2], b[nt >> 1][(nt & 1) * 2 + 1]);
        }
    }

#pragma unroll
    for (int nt = 0; nt < 8; nt++) {
        int col = n0 + wn * 64 + nt * 8 + (lane & 3) * 2;
        float2 bv = *(const float2*)(bias + col);
        if (HOUT) {
            __half* Cp = (__half*)Cout;
#pragma unroll
            for (int mt = 0; mt < 2; mt++) {
                int r = m0 + wm * 32 + mt * 16 + (lane >> 2);
                *(half2*)(Cp + (size_t)r * N + col) =
                    __floats2half2_rn(c[mt][nt][0] + bv.x, c[mt][nt][1] + bv.y);
                *(half2*)(Cp + (size_t)(r + 8) * N + col) =
                    __floats2half2_rn(c[mt][nt][2] + bv.x, c[mt][nt][3] + bv.y);
            }
        } else {
            float* Cp = (float*)Cout;
#pragma unroll
            for (int mt = 0; mt < 2; mt++) {
                int r = m0 + wm * 32 + mt * 16 + (lane >> 2);
                *(float2*)(Cp + (size_t)r * N + col) =
                    make_float2(c[mt][nt][0] + bv.x, c[mt][nt][1] + bv.y);
                *(float2*)(Cp + (size_t)(r + 8) * N + col) =
                    make_float2(c[mt][nt][2] + bv.x, c[mt][nt][3] + bv.y);
            }
        }
    }
#undef LOAD_STAGE
}

// ---------------- fused window attention (half cmb loads) ------------------
__global__ __launch_bounds__(128)
void attn_kernel() {
    __shared__ __align__(16) __half q_s[64][40];
    __shared__ __align__(16) __half k_s[64][40];
    __shared__ __align__(16) __half v_s[64][40];

    const int tid = threadIdx.x, lane = tid & 31, warp = tid >> 5;
    const int h = blockIdx.x, b = blockIdx.y, w = b & (NWIN - 1);

    const __half* base = g_qkv_h + (size_t)b * NTOK * 3 * CDIM + h * 32;

    {
        int rr = tid >> 1, hc = (tid & 1) * 16;
        const __half* gp = base + (size_t)rr * (3 * CDIM);
        *(uint4*)&q_s[rr][hc]     = *(const uint4*)(gp + hc);
        *(uint4*)&q_s[rr][hc + 8] = *(const uint4*)(gp + hc + 8);
        *(uint4*)&k_s[rr][hc]     = *(const uint4*)(gp + CDIM + hc);
        *(uint4*)&k_s[rr][hc + 8] = *(const uint4*)(gp + CDIM + hc + 8);
        *(uint4*)&v_s[rr][hc]     = *(const uint4*)(gp + 2 * CDIM + hc);
        *(uint4*)&v_s[rr][hc + 8] = *(const uint4*)(gp + 2 * CDIM + hc + 8);
    }
    __syncthreads();

    float sc[8][4];
#pragma unroll
    for (int nt = 0; nt < 8; nt++)
#pragma unroll
        for (int r = 0; r < 4; r++) sc[nt][r] = 0.f;

    uint32_t qa = s2u(q_s) + (warp * 16 + (lane & 15)) * 80 + (lane >> 4) * 16;
    uint32_t ka = s2u(k_s) + ((lane & 7) + ((lane >> 4) & 1) * 8) * 80 + ((lane >> 3) & 1) * 16;
#pragma unroll
    for (int ks = 0; ks < 2; ks++) {
        uint32_t aq[4];
        ldsm4(aq, qa + ks * 32);
        uint32_t bk[4][4];
#pragma unroll
        for (int jt = 0; jt < 4; jt++) ldsm4(bk[jt], ka + jt * 16 * 80 + ks * 32);
#pragma unroll
        for (int nt = 0; nt < 8; nt++)
            mma_f16(sc[nt], aq, bk[nt >> 1][(nt & 1) * 2], bk[nt >> 1][(nt & 1) * 2 + 1]);
    }

    const float scale = 0.17677669529663687f;   // 32^-0.5
    const int r = warp * 16 + (lane >> 2);
    {
        const __half* cmb = g_cmb_h + ((size_t)(w * HEADS + h) << 12);
#pragma unroll
        for (int nt = 0; nt < 8; nt++) {
            int col = nt * 8 + (lane & 3) * 2;
            float2 c0 = __half22float2(*(const half2*)(cmb + r * 64 + col));
            sc[nt][0] = fmaf(sc[nt][0], scale, c0.x);
            sc[nt][1] = fmaf(sc[nt][1], scale, c0.y);
            float2 c1 = __half22float2(*(const half2*)(cmb + (r + 8) * 64 + col));
            sc[nt][2] = fmaf(sc[nt][2], scale, c1.x);
            sc[nt][3] = fmaf(sc[nt][3], scale, c1.y);
        }
    }

    float mx0 = -1e30f, mx1 = -1e30f;
#pragma unroll
    for (int nt = 0; nt < 8; nt++) {
        mx0 = fmaxf(mx0, fmaxf(sc[nt][0], sc[nt][1]));
        mx1 = fmaxf(mx1, fmaxf(sc[nt][2], sc[nt][3]));
    }
    mx0 = fmaxf(mx0, __shfl_xor_sync(0xffffffff, mx0, 1));
    mx0 = fmaxf(mx0, __shfl_xor_sync(0xffffffff, mx0, 2));
    mx1 = fmaxf(mx1, __shfl_xor_sync(0xffffffff, mx1, 1));
    mx1 = fmaxf(mx1, __shfl_xor_sync(0xffffffff, mx1, 2));

    float s0 = 0.f, s1 = 0.f;
#pragma unroll
    for (int nt = 0; nt < 8; nt++) {
        sc[nt][0] = __expf(sc[nt][0] - mx0);
        sc[nt][1] = __expf(sc[nt][1] - mx0);
        s0 += sc[nt][0] + sc[nt][1];
        sc[nt][2] = __expf(sc[nt][2] - mx1);
        sc[nt][3] = __expf(sc[nt][3] - mx1);
        s1 += sc[nt][2] + sc[nt][3];
    }
    s0 += __shfl_xor_sync(0xffffffff, s0, 1);
    s0 += __shfl_xor_sync(0xffffffff, s0, 2);
    s1 += __shfl_xor_sync(0xffffffff, s1, 1);
    s1 += __shfl_xor_sync(0xffffffff, s1, 2);
    const float inv0 = 1.f / s0, inv1 = 1.f / s1;

    float oc[4][4];
#pragma unroll
    for (int nt = 0; nt < 4; nt++)
#pragma unroll
        for (int rr = 0; rr < 4; rr++) oc[nt][rr] = 0.f;

    uint32_t va = s2u(v_s) + ((lane & 7) + ((lane >> 3) & 1) * 8) * 80 + ((lane >> 4) & 1) * 16;
#pragma unroll
    for (int ks = 0; ks < 4; ks++) {
        uint32_t ap[4];
        ap[0] = pack_h2(sc[2 * ks][0],     sc[2 * ks][1]);
        ap[1] = pack_h2(sc[2 * ks][2],     sc[2 * ks][3]);
        ap[2] = pack_h2(sc[2 * ks + 1][0], sc[2 * ks + 1][1]);
        ap[3] = pack_h2(sc[2 * ks + 1][2], sc[2 * ks + 1][3]);
        uint32_t bv[2][4];
        ldsm4t(bv[0], va + ks * 16 * 80);
        ldsm4t(bv[1], va + ks * 16 * 80 + 32);
#pragma unroll
        for (int nt = 0; nt < 4; nt++)
            mma_f16(oc[nt], ap, bv[nt >> 1][(nt & 1) * 2], bv[nt >> 1][(nt & 1) * 2 + 1]);
    }

    __half* op = g_att_h + (size_t)b * NTOK * CDIM + h * 32;
#pragma unroll
    for (int nt = 0; nt < 4; nt++) {
        int d = nt * 8 + (lane & 3) * 2;
        *(half2*)(op + (size_t)r * CDIM + d) =
            __floats2half2_rn(oc[nt][0] * inv0, oc[nt][1] * inv0);
        *(half2*)(op + (size_t)(r + 8) * CDIM + d) =
            __floats2half2_rn(oc[nt][2] * inv1, oc[nt][3] * inv1);
    }
}

// ---------------- launcher ----------------
extern "C" void kernel_launch(void* const* d_in, const int* in_sizes, int n_in,
                              void* d_out, int out_size) {
    const float* x         = (const float*)d_in[0];
    const float* mask      = (const float*)d_in[1];
    const float* qkv_w     = (const float*)d_in[2];
    const float* q_bias    = (const float*)d_in[3];
    const float* v_bias    = (const float*)d_in[4];
    const float* rpb_table = (const float*)d_in[5];
    const float* proj_w    = (const float*)d_in[6];
    const float* proj_b    = (const float*)d_in[7];
    const int*   rel_index = (const int*)d_in[8];
    float* out = (float*)d_out;

    void *p_xh, *p_qkvh, *p_atth, *p_wqkv, *p_wproj, *p_qkvb;
    cudaGetSymbolAddress(&p_xh,    g_x_h);
    cudaGetSymbolAddress(&p_qkvh,  g_qkv_h);
    cudaGetSymbolAddress(&p_atth,  g_att_h);
    cudaGetSymbolAddress(&p_wqkv,  g_wqkv_h);
    cudaGetSymbolAddress(&p_wproj, g_wproj_h);
    cudaGetSymbolAddress(&p_qkvb,  g_qkvb);

    cudaFuncSetAttribute(gemm_h<true>,  cudaFuncAttributeMaxDynamicSharedMemorySize, GEMM_SMEM);
    cudaFuncSetAttribute(gemm_h<false>, cudaFuncAttributeMaxDynamicSharedMemorySize, GEMM_SMEM);

    // idx 0: qkv bias vector
    prep_bias<<<6, 256>>>(q_bias, v_bias);
    // idx 1: rpb gather (needed by big_prep's cmb section)
    prep_rpb<<<256, 256>>>(rpb_table, rel_index);
    // idx 2: fused cvt_x + cmb(half) + cvt_wqkv + cvt_wproj
    big_prep<<<XB + PB + WB + WB2, 256>>>(x, mask, qkv_w, proj_w);

    // idx 3 (ncu capture slot): QKV GEMM -> g_qkv_h
    gemm_h<true><<<dim3(1536 / 128, MROWS / 128), 256, GEMM_SMEM>>>(
        (const __half*)p_xh, (const __half*)p_wqkv, (const float*)p_qkvb,
        p_qkvh, 3 * CDIM, CDIM);

    // idx 4: fused window attention -> g_att_h
    attn_kernel<<<dim3(HEADS, BWIN), 128>>>();

    // idx 5: proj GEMM -> out (fp32)
    gemm_h<false><<<dim3(CDIM / 128, MROWS / 128), 256, GEMM_SMEM>>>(
        (const __half*)p_atth, (const __half*)p_wproj, proj_b,
        out, CDIM, CDIM);
}

// round 12
// speedup vs baseline: 1.5472x; 1.0292x over previous
#include <cuda_runtime.h>
#include <cuda_fp16.h>
#include <cstdint>

#define HEADS 16
#define CDIM  512
#define NTOK  64
#define BWIN  2048
#define NWIN  256
#define MROWS (BWIN * NTOK)        // 131072

// ---------------- static scratch ----------------
__device__ __half g_x_h[(size_t)MROWS * CDIM];          // x in half
__device__ __half g_qkv_h[(size_t)MROWS * 3 * CDIM];    // qkv in half
__device__ __half g_att_h[(size_t)MROWS * CDIM];        // attn out in half
__device__ __half g_wqkv_h[3 * CDIM * CDIM];
__device__ __half g_wproj_h[CDIM * CDIM];
__device__ float  g_rpb[HEADS * NTOK * NTOK];
__device__ __half g_cmb_h[(size_t)NWIN * HEADS * NTOK * NTOK];  // rpb+mask, half (32MB)
__device__ float  g_qkvb[3 * CDIM];

// ---------------- helpers ----------------
__device__ __forceinline__ uint32_t s2u(const void* p) {
    uint32_t a;
    asm("{ .reg .u64 t; cvta.to.shared.u64 t, %1; cvt.u32.u64 %0, t; }" : "=r"(a) : "l"(p));
    return a;
}
__device__ __forceinline__ void cpa16(uint32_t dst, const void* src) {
    asm volatile("cp.async.cg.shared.global [%0], [%1], 16;" :: "r"(dst), "l"(src) : "memory");
}
__device__ __forceinline__ void ldsm4(uint32_t r[4], uint32_t a) {
    asm volatile("ldmatrix.sync.aligned.m8n8.x4.shared.b16 {%0,%1,%2,%3}, [%4];"
                 : "=r"(r[0]), "=r"(r[1]), "=r"(r[2]), "=r"(r[3]) : "r"(a));
}
__device__ __forceinline__ void ldsm4t(uint32_t r[4], uint32_t a) {
    asm volatile("ldmatrix.sync.aligned.m8n8.x4.trans.shared.b16 {%0,%1,%2,%3}, [%4];"
                 : "=r"(r[0]), "=r"(r[1]), "=r"(r[2]), "=r"(r[3]) : "r"(a));
}
__device__ __forceinline__ void mma_f16(float c[4], const uint32_t a[4],
                                        uint32_t b0, uint32_t b1) {
    asm volatile(
        "mma.sync.aligned.m16n8k16.row.col.f32.f16.f16.f32 "
        "{%0,%1,%2,%3}, {%4,%5,%6,%7}, {%8,%9}, {%0,%1,%2,%3};"
        : "+f"(c[0]), "+f"(c[1]), "+f"(c[2]), "+f"(c[3])
        : "r"(a[0]), "r"(a[1]), "r"(a[2]), "r"(a[3]), "r"(b0), "r"(b1));
}
__device__ __forceinline__ uint32_t pack_h2(float a, float b) {
    half2 h = __floats2half2_rn(a, b);
    return *reinterpret_cast<uint32_t*>(&h);
}

// ---------------- prep: rpb gather + qkv bias (merged) ----------------
__global__ void prep_rpb_bias(const float* __restrict__ rpb_table,
                              const int*   __restrict__ rel_index,
                              const float* __restrict__ q_bias,
                              const float* __restrict__ v_bias) {
    int idx = blockIdx.x * 256 + threadIdx.x;   // grid 256 -> 65536
    int h  = idx >> 12;
    int nm = idx & 4095;
    g_rpb[idx] = rpb_table[rel_index[nm] * HEADS + h];
    if (idx < 3 * CDIM) {
        float v = 0.f;
        if (idx < CDIM)           v = q_bias[idx];
        else if (idx >= 2 * CDIM) v = v_bias[idx - 2 * CDIM];
        g_qkvb[idx] = v;
    }
}

// ---------------- big_prep: cvt x, cmb(half), cvt wqkv, cvt wproj ----------
#define XB   65536        // x cvt       (16777216 float4 / 256)
#define PB   16384        // cmb         (4194304 float4 / 256)
#define WB   768          // wqkv cvt    (196608 float4 / 256)
#define WB2  256          // wproj cvt   (65536 float4 / 256)
__global__ void big_prep(const float* __restrict__ x,
                         const float* __restrict__ mask,
                         const float* __restrict__ qkv_w,
                         const float* __restrict__ proj_w) {
    int bid = blockIdx.x;
    if (bid < XB) {
        int i = bid * 256 + threadIdx.x;
        float4 v = ((const float4*)x)[i];
        ((half2*)g_x_h)[2 * i]     = __floats2half2_rn(v.x, v.y);
        ((half2*)g_x_h)[2 * i + 1] = __floats2half2_rn(v.z, v.w);
    } else if (bid < XB + PB) {
        int i = (bid - XB) * 256 + threadIdx.x;      // float4 index
        int nm4 = i & 1023;
        int wh  = i >> 10;
        int h = wh & (HEADS - 1), w = wh >> 4;
        float4 rb = ((const float4*)g_rpb)[(h << 10) + nm4];
        float4 mk = ((const float4*)mask)[((size_t)w << 10) + nm4];
        ((half2*)g_cmb_h)[2 * i]     = __floats2half2_rn(rb.x + mk.x, rb.y + mk.y);
        ((half2*)g_cmb_h)[2 * i + 1] = __floats2half2_rn(rb.z + mk.z, rb.w + mk.w);
    } else if (bid < XB + PB + WB) {
        int i = (bid - XB - PB) * 256 + threadIdx.x;
        float4 v = ((const float4*)qkv_w)[i];
        ((half2*)g_wqkv_h)[2 * i]     = __floats2half2_rn(v.x, v.y);
        ((half2*)g_wqkv_h)[2 * i + 1] = __floats2half2_rn(v.z, v.w);
    } else {
        int i = (bid - XB - PB - WB) * 256 + threadIdx.x;
        float4 v = ((const float4*)proj_w)[i];
        ((half2*)g_wproj_h)[2 * i]     = __floats2half2_rn(v.x, v.y);
        ((half2*)g_wproj_h)[2 * i + 1] = __floats2half2_rn(v.z, v.w);
    }
}

// ---------------- fp16 GEMM (R6 8-warp): C = A*B^T + bias ----------------
#define BK      64
#define ROW_B   144
#define STG_A   (128 * ROW_B)
#define STG     (2 * STG_A)
#define NSTG    3
#define GEMM_SMEM (NSTG * STG)      // 110592

template<bool HOUT>
__global__ __launch_bounds__(256, 2)
void gemm_h(const __half* __restrict__ A, const __half* __restrict__ B,
            const float* __restrict__ bias, void* __restrict__ Cout,
            int N, int K) {
    extern __shared__ __align__(16) char smem[];
    const uint32_t sb = s2u(smem);
    const int tid = threadIdx.x, lane = tid & 31, warp = tid >> 5;
    const int wm = warp & 3, wn = warp >> 2;
    const int m0 = blockIdx.y * 128, n0 = blockIdx.x * 128;

    const __half* Ag = A + (size_t)m0 * K;
    const __half* Bg = B + (size_t)n0 * K;

    float c[2][8][4];
#pragma unroll
    for (int mt = 0; mt < 2; mt++)
#pragma unroll
        for (int nt = 0; nt < 8; nt++)
#pragma unroll
            for (int r = 0; r < 4; r++) c[mt][nt][r] = 0.f;

#define LOAD_STAGE(s, kb) do { \
    _Pragma("unroll") \
    for (int i = 0; i < 4; i++) { \
        int f = tid + 256 * i; \
        int row = f >> 3; int cc = f & 7; \
        cpa16(sb + (s) * STG + row * ROW_B + cc * 16, \
              Ag + (size_t)(kb) * BK + (size_t)row * K + cc * 8); \
        cpa16(sb + (s) * STG + STG_A + row * ROW_B + cc * 16, \
              Bg + (size_t)(kb) * BK + (size_t)row * K + cc * 8); \
    } \
    asm volatile("cp.async.commit_group;" ::: "memory"); \
} while (0)

    LOAD_STAGE(0, 0);
    LOAD_STAGE(1, 1);

    const uint32_t aoff = (wm * 32 + (lane & 15)) * ROW_B + (lane >> 4) * 16;
    const uint32_t boff = STG_A + (wn * 64 + (lane & 7) + ((lane >> 4) & 1) * 8) * ROW_B
                          + ((lane >> 3) & 1) * 16;
    const int KB = K / BK;   // 8

    for (int kb = 0; kb < KB; kb++) {
        if (kb + 2 < KB) asm volatile("cp.async.wait_group 1;" ::: "memory");
        else             asm volatile("cp.async.wait_group 0;" ::: "memory");
        __syncthreads();
        if (kb + 2 < KB) { int s = (kb + 2) % NSTG; LOAD_STAGE(s, kb + 2); }

        uint32_t ab = sb + (kb % NSTG) * STG + aoff;
        uint32_t bb = sb + (kb % NSTG) * STG + boff;
#pragma unroll
        for (int ks = 0; ks < 4; ks++) {
            uint32_t a[2][4], b[4][4];
#pragma unroll
            for (int mt = 0; mt < 2; mt++) ldsm4(a[mt], ab + mt * 16 * ROW_B + ks * 32);
#pragma unroll
            for (int jt = 0; jt < 4; jt++) ldsm4(b[jt], bb + jt * 16 * ROW_B + ks * 32);
#pragma unroll
            for (int mt = 0; mt < 2; mt++)
#pragma unroll
                for (int nt = 0; nt < 8; nt++)
                    mma_f16(c[mt][nt], a[mt], b[nt >> 1][(nt & 1) * 2], b[nt >> 1][(nt & 1) * 2 + 1]);
        }
    }

#pragma unroll
    for (int nt = 0; nt < 8; nt++) {
        int col = n0 + wn * 64 + nt * 8 + (lane & 3) * 2;
        float2 bv = *(const float2*)(bias + col);
        if (HOUT) {
            __half* Cp = (__half*)Cout;
#pragma unroll
            for (int mt = 0; mt < 2; mt++) {
                int r = m0 + wm * 32 + mt * 16 + (lane >> 2);
                *(half2*)(Cp + (size_t)r * N + col) =
                    __floats2half2_rn(c[mt][nt][0] + bv.x, c[mt][nt][1] + bv.y);
                *(half2*)(Cp + (size_t)(r + 8) * N + col) =
                    __floats2half2_rn(c[mt][nt][2] + bv.x, c[mt][nt][3] + bv.y);
            }
        } else {
            float* Cp = (float*)Cout;
#pragma unroll
            for (int mt = 0; mt < 2; mt++) {
                int r = m0 + wm * 32 + mt * 16 + (lane >> 2);
                *(float2*)(Cp + (size_t)r * N + col) =
                    make_float2(c[mt][nt][0] + bv.x, c[mt][nt][1] + bv.y);
                *(float2*)(Cp + (size_t)(r + 8) * N + col) =
                    make_float2(c[mt][nt][2] + bv.x, c[mt][nt][3] + bv.y);
            }
        }
    }
#undef LOAD_STAGE
}

// ---------------- fused window attention: 4 heads per CTA, 512 threads -----
// warp w handles head (w>>2), query rows ((w&3)*16 .. +16). Per-warp math is
// the R11-proven code. Coalesced q/k/v loads: 256B contiguous per row.
#define HSTR_H 2592                     // halves per head block (5184B; mod128=64)
#define TEN_H  (4 * HSTR_H)             // halves per tensor block
#define ATTN_SMEM (3 * TEN_H * 2)       // 62208 bytes

__global__ __launch_bounds__(512, 2)
void attn_kernel() {
    extern __shared__ __align__(16) __half smh[];
    const int tid = threadIdx.x, lane = tid & 31, warp = tid >> 5;
    const int head = warp >> 2;                 // 0..3
    const int h = blockIdx.x * 4 + head;        // global head
    const int b = blockIdx.y, w = b & (NWIN - 1);

    // ---- coalesced load of q,k,v for 4 heads (256B contiguous per row) ----
    {
        const __half* rowbase = g_qkv_h + (size_t)b * NTOK * 3 * CDIM + blockIdx.x * 128;
#pragma unroll
        for (int i = 0; i < 2; i++) {
            int c  = tid + 512 * i;             // 0..1023
            int rr = c >> 4, cc = c & 15;
            int hd = cc >> 2, hcol = (cc & 3) * 8;
            const __half* gp = rowbase + (size_t)rr * (3 * CDIM) + cc * 8;
            int dst = hd * HSTR_H + rr * 40 + hcol;
            *(uint4*)(smh + dst)             = *(const uint4*)(gp);
            *(uint4*)(smh + TEN_H + dst)     = *(const uint4*)(gp + CDIM);
            *(uint4*)(smh + 2 * TEN_H + dst) = *(const uint4*)(gp + 2 * CDIM);
        }
    }
    __syncthreads();

    const uint32_t hb = s2u(smh) + head * (HSTR_H * 2);   // byte base of this head's q
    const int rbase = (warp & 3) * 16;

    // ---- S = Q K^T ----
    float sc[8][4];
#pragma unroll
    for (int nt = 0; nt < 8; nt++)
#pragma unroll
        for (int r = 0; r < 4; r++) sc[nt][r] = 0.f;

    uint32_t qa = hb + (rbase + (lane & 15)) * 80 + (lane >> 4) * 16;
    uint32_t ka = hb + (TEN_H * 2) + ((lane & 7) + ((lane >> 4) & 1) * 8) * 80
                  + ((lane >> 3) & 1) * 16;
#pragma unroll
    for (int ks = 0; ks < 2; ks++) {
        uint32_t aq[4];
        ldsm4(aq, qa + ks * 32);
        uint32_t bk[4][4];
#pragma unroll
        for (int jt = 0; jt < 4; jt++) ldsm4(bk[jt], ka + jt * 16 * 80 + ks * 32);
#pragma unroll
        for (int nt = 0; nt < 8; nt++)
            mma_f16(sc[nt], aq, bk[nt >> 1][(nt & 1) * 2], bk[nt >> 1][(nt & 1) * 2 + 1]);
    }

    // ---- scale + combined (rpb+mask) half bias ----
    const float scale = 0.17677669529663687f;   // 32^-0.5
    const int r = rbase + (lane >> 2);
    {
        const __half* cmb = g_cmb_h + ((size_t)(w * HEADS + h) << 12);
#pragma unroll
        for (int nt = 0; nt < 8; nt++) {
            int col = nt * 8 + (lane & 3) * 2;
            float2 c0 = __half22float2(*(const half2*)(cmb + r * 64 + col));
            sc[nt][0] = fmaf(sc[nt][0], scale, c0.x);
            sc[nt][1] = fmaf(sc[nt][1], scale, c0.y);
            float2 c1 = __half22float2(*(const half2*)(cmb + (r + 8) * 64 + col));
            sc[nt][2] = fmaf(sc[nt][2], scale, c1.x);
            sc[nt][3] = fmaf(sc[nt][3], scale, c1.y);
        }
    }

    // ---- softmax in registers ----
    float mx0 = -1e30f, mx1 = -1e30f;
#pragma unroll
    for (int nt = 0; nt < 8; nt++) {
        mx0 = fmaxf(mx0, fmaxf(sc[nt][0], sc[nt][1]));
        mx1 = fmaxf(mx1, fmaxf(sc[nt][2], sc[nt][3]));
    }
    mx0 = fmaxf(mx0, __shfl_xor_sync(0xffffffff, mx0, 1));
    mx0 = fmaxf(mx0, __shfl_xor_sync(0xffffffff, mx0, 2));
    mx1 = fmaxf(mx1, __shfl_xor_sync(0xffffffff, mx1, 1));
    mx1 = fmaxf(mx1, __shfl_xor_sync(0xffffffff, mx1, 2));

    float s0 = 0.f, s1 = 0.f;
#pragma unroll
    for (int nt = 0; nt < 8; nt++) {
        sc[nt][0] = __expf(sc[nt][0] - mx0);
        sc[nt][1] = __expf(sc[nt][1] - mx0);
        s0 += sc[nt][0] + sc[nt][1];
        sc[nt][2] = __expf(sc[nt][2] - mx1);
        sc[nt][3] = __expf(sc[nt][3] - mx1);
        s1 += sc[nt][2] + sc[nt][3];
    }
    s0 += __shfl_xor_sync(0xffffffff, s0, 1);
    s0 += __shfl_xor_sync(0xffffffff, s0, 2);
    s1 += __shfl_xor_sync(0xffffffff, s1, 1);
    s1 += __shfl_xor_sync(0xffffffff, s1, 2);
    const float inv0 = 1.f / s0, inv1 = 1.f / s1;

    // ---- O = P V ----
    float oc[4][4];
#pragma unroll
    for (int nt = 0; nt < 4; nt++)
#pragma unroll
        for (int rr = 0; rr < 4; rr++) oc[nt][rr] = 0.f;

    uint32_t va = hb + (4 * TEN_H) + ((lane & 7) + ((lane >> 3) & 1) * 8) * 80
                  + ((lane >> 4) & 1) * 16;
#pragma unroll
    for (int ks = 0; ks < 4; ks++) {
        uint32_t ap[4];
        ap[0] = pack_h2(sc[2 * ks][0],     sc[2 * ks][1]);
        ap[1] = pack_h2(sc[2 * ks][2],     sc[2 * ks][3]);
        ap[2] = pack_h2(sc[2 * ks + 1][0], sc[2 * ks + 1][1]);
        ap[3] = pack_h2(sc[2 * ks + 1][2], sc[2 * ks + 1][3]);
        uint32_t bv[2][4];
        ldsm4t(bv[0], va + ks * 16 * 80);
        ldsm4t(bv[1], va + ks * 16 * 80 + 32);
#pragma unroll
        for (int nt = 0; nt < 4; nt++)
            mma_f16(oc[nt], ap, bv[nt >> 1][(nt & 1) * 2], bv[nt >> 1][(nt & 1) * 2 + 1]);
    }

    // ---- normalize + store half ----
    __half* op = g_att_h + (size_t)b * NTOK * CDIM + h * 32;
#pragma unroll
    for (int nt = 0; nt < 4; nt++) {
        int d = nt * 8 + (lane & 3) * 2;
        *(half2*)(op + (size_t)r * CDIM + d) =
            __floats2half2_rn(oc[nt][0] * inv0, oc[nt][1] * inv0);
        *(half2*)(op + (size_t)(r + 8) * CDIM + d) =
            __floats2half2_rn(oc[nt][2] * inv1, oc[nt][3] * inv1);
    }
}

// ---------------- launcher ----------------
extern "C" void kernel_launch(void* const* d_in, const int* in_sizes, int n_in,
                              void* d_out, int out_size) {
    const float* x         = (const float*)d_in[0];
    const float* mask      = (const float*)d_in[1];
    const float* qkv_w     = (const float*)d_in[2];
    const float* q_bias    = (const float*)d_in[3];
    const float* v_bias    = (const float*)d_in[4];
    const float* rpb_table = (const float*)d_in[5];
    const float* proj_w    = (const float*)d_in[6];
    const float* proj_b    = (const float*)d_in[7];
    const int*   rel_index = (const int*)d_in[8];
    float* out = (float*)d_out;

    void *p_xh, *p_qkvh, *p_atth, *p_wqkv, *p_wproj, *p_qkvb;
    cudaGetSymbolAddress(&p_xh,    g_x_h);
    cudaGetSymbolAddress(&p_qkvh,  g_qkv_h);
    cudaGetSymbolAddress(&p_atth,  g_att_h);
    cudaGetSymbolAddress(&p_wqkv,  g_wqkv_h);
    cudaGetSymbolAddress(&p_wproj, g_wproj_h);
    cudaGetSymbolAddress(&p_qkvb,  g_qkvb);

    cudaFuncSetAttribute(gemm_h<true>,  cudaFuncAttributeMaxDynamicSharedMemorySize, GEMM_SMEM);
    cudaFuncSetAttribute(gemm_h<false>, cudaFuncAttributeMaxDynamicSharedMemorySize, GEMM_SMEM);
    cudaFuncSetAttribute(attn_kernel,   cudaFuncAttributeMaxDynamicSharedMemorySize, ATTN_SMEM);

    // idx 0: rpb gather + qkv bias vector
    prep_rpb_bias<<<256, 256>>>(rpb_table, rel_index, q_bias, v_bias);
    // idx 1: fused cvt_x + cmb(half) + cvt_wqkv + cvt_wproj
    big_prep<<<XB + PB + WB + WB2, 256>>>(x, mask, qkv_w, proj_w);

    // idx 2: QKV GEMM -> g_qkv_h
    gemm_h<true><<<dim3(1536 / 128, MROWS / 128), 256, GEMM_SMEM>>>(
        (const __half*)p_xh, (const __half*)p_wqkv, (const float*)p_qkvb,
        p_qkvh, 3 * CDIM, CDIM);

    // idx 3 (ncu capture slot): fused window attention, 4 heads/CTA
    attn_kernel<<<dim3(HEADS / 4, BWIN), 512, ATTN_SMEM>>>();

    // idx 4: proj GEMM -> out (fp32)
    gemm_h<false><<<dim3(CDIM / 128, MROWS / 128), 256, GEMM_SMEM>>>(
        (const __half*)p_atth, (const __half*)p_wproj, proj_b,
        out, CDIM, CDIM);
}

// round 13
// speedup vs baseline: 1.5624x; 1.0099x over previous
#include <cuda_runtime.h>
#include <cuda_fp16.h>
#include <cstdint>

#define HEADS 16
#define CDIM  512
#define NTOK  64
#define BWIN  2048
#define NWIN  256
#define MROWS (BWIN * NTOK)        // 131072

// ---------------- static scratch ----------------
__device__ __half g_x_h[(size_t)MROWS * CDIM];          // x in half
__device__ __half g_qkv_h[(size_t)MROWS * 3 * CDIM];    // qkv in half
__device__ __half g_att_h[(size_t)MROWS * CDIM];        // attn out in half
__device__ __half g_wqkv_h[3 * CDIM * CDIM];
__device__ __half g_wproj_h[CDIM * CDIM];
__device__ float  g_rpb[HEADS * NTOK * NTOK];
__device__ __half g_cmb_h[(size_t)NWIN * HEADS * NTOK * NTOK];  // rpb+mask, half (32MB)
__device__ float  g_qkvb[3 * CDIM];

// ---------------- helpers ----------------
__device__ __forceinline__ uint32_t s2u(const void* p) {
    uint32_t a;
    asm("{ .reg .u64 t; cvta.to.shared.u64 t, %1; cvt.u32.u64 %0, t; }" : "=r"(a) : "l"(p));
    return a;
}
__device__ __forceinline__ void cpa16(uint32_t dst, const void* src) {
    asm volatile("cp.async.cg.shared.global [%0], [%1], 16;" :: "r"(dst), "l"(src) : "memory");
}
__device__ __forceinline__ void ldsm4(uint32_t r[4], uint32_t a) {
    asm volatile("ldmatrix.sync.aligned.m8n8.x4.shared.b16 {%0,%1,%2,%3}, [%4];"
                 : "=r"(r[0]), "=r"(r[1]), "=r"(r[2]), "=r"(r[3]) : "r"(a));
}
__device__ __forceinline__ void ldsm4t(uint32_t r[4], uint32_t a) {
    asm volatile("ldmatrix.sync.aligned.m8n8.x4.trans.shared.b16 {%0,%1,%2,%3}, [%4];"
                 : "=r"(r[0]), "=r"(r[1]), "=r"(r[2]), "=r"(r[3]) : "r"(a));
}
__device__ __forceinline__ void mma_f16(float c[4], const uint32_t a[4],
                                        uint32_t b0, uint32_t b1) {
    asm volatile(
        "mma.sync.aligned.m16n8k16.row.col.f32.f16.f16.f32 "
        "{%0,%1,%2,%3}, {%4,%5,%6,%7}, {%8,%9}, {%0,%1,%2,%3};"
        : "+f"(c[0]), "+f"(c[1]), "+f"(c[2]), "+f"(c[3])
        : "r"(a[0]), "r"(a[1]), "r"(a[2]), "r"(a[3]), "r"(b0), "r"(b1));
}
__device__ __forceinline__ uint32_t pack_h2(float a, float b) {
    half2 h = __floats2half2_rn(a, b);
    return *reinterpret_cast<uint32_t*>(&h);
}

// ---------------- prep: rpb gather + qkv bias (merged) ----------------
__global__ void prep_rpb_bias(const float* __restrict__ rpb_table,
                              const int*   __restrict__ rel_index,
                              const float* __restrict__ q_bias,
                              const float* __restrict__ v_bias) {
    int idx = blockIdx.x * 256 + threadIdx.x;   // grid 256 -> 65536
    int h  = idx >> 12;
    int nm = idx & 4095;
    g_rpb[idx] = rpb_table[rel_index[nm] * HEADS + h];
    if (idx < 3 * CDIM) {
        float v = 0.f;
        if (idx < CDIM)           v = q_bias[idx];
        else if (idx >= 2 * CDIM) v = v_bias[idx - 2 * CDIM];
        g_qkvb[idx] = v;
    }
}

// ---------------- big_prep: cvt x, cmb(half), cvt wqkv, cvt wproj ----------
#define XB   65536        // x cvt       (16777216 float4 / 256)
#define PB   16384        // cmb         (4194304 float4 / 256)
#define WB   768          // wqkv cvt    (196608 float4 / 256)
#define WB2  256          // wproj cvt   (65536 float4 / 256)
__global__ void big_prep(const float* __restrict__ x,
                         const float* __restrict__ mask,
                         const float* __restrict__ qkv_w,
                         const float* __restrict__ proj_w) {
    int bid = blockIdx.x;
    if (bid < XB) {
        int i = bid * 256 + threadIdx.x;
        float4 v = ((const float4*)x)[i];
        ((half2*)g_x_h)[2 * i]     = __floats2half2_rn(v.x, v.y);
        ((half2*)g_x_h)[2 * i + 1] = __floats2half2_rn(v.z, v.w);
    } else if (bid < XB + PB) {
        int i = (bid - XB) * 256 + threadIdx.x;      // float4 index
        int nm4 = i & 1023;
        int wh  = i >> 10;
        int h = wh & (HEADS - 1), w = wh >> 4;
        float4 rb = ((const float4*)g_rpb)[(h << 10) + nm4];
        float4 mk = ((const float4*)mask)[((size_t)w << 10) + nm4];
        ((half2*)g_cmb_h)[2 * i]     = __floats2half2_rn(rb.x + mk.x, rb.y + mk.y);
        ((half2*)g_cmb_h)[2 * i + 1] = __floats2half2_rn(rb.z + mk.z, rb.w + mk.w);
    } else if (bid < XB + PB + WB) {
        int i = (bid - XB - PB) * 256 + threadIdx.x;
        float4 v = ((const float4*)qkv_w)[i];
        ((half2*)g_wqkv_h)[2 * i]     = __floats2half2_rn(v.x, v.y);
        ((half2*)g_wqkv_h)[2 * i + 1] = __floats2half2_rn(v.z, v.w);
    } else {
        int i = (bid - XB - PB - WB) * 256 + threadIdx.x;
        float4 v = ((const float4*)proj_w)[i];
        ((half2*)g_wproj_h)[2 * i]     = __floats2half2_rn(v.x, v.y);
        ((half2*)g_wproj_h)[2 * i + 1] = __floats2half2_rn(v.z, v.w);
    }
}

// ---------------- fp16 GEMM (R6 8-warp): C = A*B^T + bias ----------------
#define BK      64
#define ROW_B   144
#define STG_A   (128 * ROW_B)
#define STG     (2 * STG_A)
#define NSTG    3
#define GEMM_SMEM (NSTG * STG)      // 110592

template<bool HOUT>
__global__ __launch_bounds__(256, 2)
void gemm_h(const __half* __restrict__ A, const __half* __restrict__ B,
            const float* __restrict__ bias, void* __restrict__ Cout,
            int N, int K) {
    extern __shared__ __align__(16) char smem[];
    const uint32_t sb = s2u(smem);
    const int tid = threadIdx.x, lane = tid & 31, warp = tid >> 5;
    const int wm = warp & 3, wn = warp >> 2;
    const int m0 = blockIdx.y * 128, n0 = blockIdx.x * 128;

    const __half* Ag = A + (size_t)m0 * K;
    const __half* Bg = B + (size_t)n0 * K;

    float c[2][8][4];
#pragma unroll
    for (int mt = 0; mt < 2; mt++)
#pragma unroll
        for (int nt = 0; nt < 8; nt++)
#pragma unroll
            for (int r = 0; r < 4; r++) c[mt][nt][r] = 0.f;

#define LOAD_STAGE(s, kb) do { \
    _Pragma("unroll") \
    for (int i = 0; i < 4; i++) { \
        int f = tid + 256 * i; \
        int row = f >> 3; int cc = f & 7; \
        cpa16(sb + (s) * STG + row * ROW_B + cc * 16, \
              Ag + (size_t)(kb) * BK + (size_t)row * K + cc * 8); \
        cpa16(sb + (s) * STG + STG_A + row * ROW_B + cc * 16, \
              Bg + (size_t)(kb) * BK + (size_t)row * K + cc * 8); \
    } \
    asm volatile("cp.async.commit_group;" ::: "memory"); \
} while (0)

    LOAD_STAGE(0, 0);
    LOAD_STAGE(1, 1);

    const uint32_t aoff = (wm * 32 + (lane & 15)) * ROW_B + (lane >> 4) * 16;
    const uint32_t boff = STG_A + (wn * 64 + (lane & 7) + ((lane >> 4) & 1) * 8) * ROW_B
                          + ((lane >> 3) & 1) * 16;
    const int KB = K / BK;   // 8

    for (int kb = 0; kb < KB; kb++) {
        if (kb + 2 < KB) asm volatile("cp.async.wait_group 1;" ::: "memory");
        else             asm volatile("cp.async.wait_group 0;" ::: "memory");
        __syncthreads();
        if (kb + 2 < KB) { int s = (kb + 2) % NSTG; LOAD_STAGE(s, kb + 2); }

        uint32_t ab = sb + (kb % NSTG) * STG + aoff;
        uint32_t bb = sb + (kb % NSTG) * STG + boff;
#pragma unroll
        for (int ks = 0; ks < 4; ks++) {
            uint32_t a[2][4], b[4][4];
#pragma unroll
            for (int mt = 0; mt < 2; mt++) ldsm4(a[mt], ab + mt * 16 * ROW_B + ks * 32);
#pragma unroll
            for (int jt = 0; jt < 4; jt++) ldsm4(b[jt], bb + jt * 16 * ROW_B + ks * 32);
#pragma unroll
            for (int mt = 0; mt < 2; mt++)
#pragma unroll
                for (int nt = 0; nt < 8; nt++)
                    mma_f16(c[mt][nt], a[mt], b[nt >> 1][(nt & 1) * 2], b[nt >> 1][(nt & 1) * 2 + 1]);
        }
    }

#pragma unroll
    for (int nt = 0; nt < 8; nt++) {
        int col = n0 + wn * 64 + nt * 8 + (lane & 3) * 2;
        float2 bv = *(const float2*)(bias + col);
        if (HOUT) {
            __half* Cp = (__half*)Cout;
#pragma unroll
            for (int mt = 0; mt < 2; mt++) {
                int r = m0 + wm * 32 + mt * 16 + (lane >> 2);
                *(half2*)(Cp + (size_t)r * N + col) =
                    __floats2half2_rn(c[mt][nt][0] + bv.x, c[mt][nt][1] + bv.y);
                *(half2*)(Cp + (size_t)(r + 8) * N + col) =
                    __floats2half2_rn(c[mt][nt][2] + bv.x, c[mt][nt][3] + bv.y);
            }
        } else {
            float* Cp = (float*)Cout;
#pragma unroll
            for (int mt = 0; mt < 2; mt++) {
                int r = m0 + wm * 32 + mt * 16 + (lane >> 2);
                *(float2*)(Cp + (size_t)r * N + col) =
                    make_float2(c[mt][nt][0] + bv.x, c[mt][nt][1] + bv.y);
                *(float2*)(Cp + (size_t)(r + 8) * N + col) =
                    make_float2(c[mt][nt][2] + bv.x, c[mt][nt][3] + bv.y);
            }
        }
    }
#undef LOAD_STAGE
}

// ---------------- fused window attention: 4 heads/CTA + smem-staged cmb ----
// warp w handles head (w>>2), query rows ((w&3)*16 .. +16).
// cmb tiles (4 x 64x64 half) cp.async-staged, conflict-free LDS in epilogue.
#define HSTR_H 2592                     // halves per head block (5184B; mod128=64)
#define TEN_H  (4 * HSTR_H)             // halves per tensor block (q,k,v each)
#define CMB_OFF (3 * TEN_H)             // halves offset of cmb region
#define CMB_ROW 72                      // halves per cmb row (144B)
#define CMB_HEAD (64 * CMB_ROW)         // 4608 halves per head tile
#define ATTN_SMEM ((CMB_OFF + 4 * CMB_HEAD) * 2)   // 62208 + 36864 = 99072 B

__global__ __launch_bounds__(512, 2)
void attn_kernel() {
    extern __shared__ __align__(16) __half smh[];
    const int tid = threadIdx.x, lane = tid & 31, warp = tid >> 5;
    const int head = warp >> 2;                 // 0..3
    const int h = blockIdx.x * 4 + head;        // global head
    const int b = blockIdx.y, w = b & (NWIN - 1);

    // ---- cp.async stage of 4 cmb tiles (64x64 half each; 16B coalesced) ----
    {
        const __half* cmbg = g_cmb_h + ((size_t)(w * HEADS + blockIdx.x * 4) << 12);
        uint32_t cbase = s2u(smh) + CMB_OFF * 2;
#pragma unroll
        for (int i = 0; i < 4; i++) {
            int c   = tid + 512 * i;            // 0..2047
            int tl  = c >> 9;                   // head tile 0..3
            int rr  = (c >> 3) & 63;
            int cc  = c & 7;
            cpa16(cbase + (tl * CMB_HEAD + rr * CMB_ROW) * 2 + cc * 16,
                  cmbg + ((size_t)tl << 12) + rr * 64 + cc * 8);
        }
        asm volatile("cp.async.commit_group;" ::: "memory");
    }

    // ---- coalesced load of q,k,v for 4 heads (256B contiguous per row) ----
    {
        const __half* rowbase = g_qkv_h + (size_t)b * NTOK * 3 * CDIM + blockIdx.x * 128;
#pragma unroll
        for (int i = 0; i < 2; i++) {
            int c  = tid + 512 * i;             // 0..1023
            int rr = c >> 4, cc = c & 15;
            int hd = cc >> 2, hcol = (cc & 3) * 8;
            const __half* gp = rowbase + (size_t)rr * (3 * CDIM) + cc * 8;
            int dst = hd * HSTR_H + rr * 40 + hcol;
            *(uint4*)(smh + dst)             = *(const uint4*)(gp);
            *(uint4*)(smh + TEN_H + dst)     = *(const uint4*)(gp + CDIM);
            *(uint4*)(smh + 2 * TEN_H + dst) = *(const uint4*)(gp + 2 * CDIM);
        }
    }
    asm volatile("cp.async.wait_group 0;" ::: "memory");
    __syncthreads();

    const uint32_t hb = s2u(smh) + head * (HSTR_H * 2);   // byte base of this head's q
    const int rbase = (warp & 3) * 16;

    // ---- S = Q K^T ----
    float sc[8][4];
#pragma unroll
    for (int nt = 0; nt < 8; nt++)
#pragma unroll
        for (int r = 0; r < 4; r++) sc[nt][r] = 0.f;

    uint32_t qa = hb + (rbase + (lane & 15)) * 80 + (lane >> 4) * 16;
    uint32_t ka = hb + (TEN_H * 2) + ((lane & 7) + ((lane >> 4) & 1) * 8) * 80
                  + ((lane >> 3) & 1) * 16;
#pragma unroll
    for (int ks = 0; ks < 2; ks++) {
        uint32_t aq[4];
        ldsm4(aq, qa + ks * 32);
        uint32_t bk[4][4];
#pragma unroll
        for (int jt = 0; jt < 4; jt++) ldsm4(bk[jt], ka + jt * 16 * 80 + ks * 32);
#pragma unroll
        for (int nt = 0; nt < 8; nt++)
            mma_f16(sc[nt], aq, bk[nt >> 1][(nt & 1) * 2], bk[nt >> 1][(nt & 1) * 2 + 1]);
    }

    // ---- scale + combined (rpb+mask) bias from smem (conflict-free LDS) ----
    const float scale = 0.17677669529663687f;   // 32^-0.5
    const int r = rbase + (lane >> 2);
    {
        const __half* cmbs = smh + CMB_OFF + head * CMB_HEAD;
#pragma unroll
        for (int nt = 0; nt < 8; nt++) {
            int col = nt * 8 + (lane & 3) * 2;
            float2 c0 = __half22float2(*(const half2*)(cmbs + r * CMB_ROW + col));
            sc[nt][0] = fmaf(sc[nt][0], scale, c0.x);
            sc[nt][1] = fmaf(sc[nt][1], scale, c0.y);
            float2 c1 = __half22float2(*(const half2*)(cmbs + (r + 8) * CMB_ROW + col));
            sc[nt][2] = fmaf(sc[nt][2], scale, c1.x);
            sc[nt][3] = fmaf(sc[nt][3], scale, c1.y);
        }
    }

    // ---- softmax in registers ----
    float mx0 = -1e30f, mx1 = -1e30f;
#pragma unroll
    for (int nt = 0; nt < 8; nt++) {
        mx0 = fmaxf(mx0, fmaxf(sc[nt][0], sc[nt][1]));
        mx1 = fmaxf(mx1, fmaxf(sc[nt][2], sc[nt][3]));
    }
    mx0 = fmaxf(mx0, __shfl_xor_sync(0xffffffff, mx0, 1));
    mx0 = fmaxf(mx0, __shfl_xor_sync(0xffffffff, mx0, 2));
    mx1 = fmaxf(mx1, __shfl_xor_sync(0xffffffff, mx1, 1));
    mx1 = fmaxf(mx1, __shfl_xor_sync(0xffffffff, mx1, 2));

    float s0 = 0.f, s1 = 0.f;
#pragma unroll
    for (int nt = 0; nt < 8; nt++) {
        sc[nt][0] = __expf(sc[nt][0] - mx0);
        sc[nt][1] = __expf(sc[nt][1] - mx0);
        s0 += sc[nt][0] + sc[nt][1];
        sc[nt][2] = __expf(sc[nt][2] - mx1);
        sc[nt][3] = __expf(sc[nt][3] - mx1);
        s1 += sc[nt][2] + sc[nt][3];
    }
    s0 += __shfl_xor_sync(0xffffffff, s0, 1);
    s0 += __shfl_xor_sync(0xffffffff, s0, 2);
    s1 += __shfl_xor_sync(0xffffffff, s1, 1);
    s1 += __shfl_xor_sync(0xffffffff, s1, 2);
    const float inv0 = 1.f / s0, inv1 = 1.f / s1;

    // ---- O = P V ----
    float oc[4][4];
#pragma unroll
    for (int nt = 0; nt < 4; nt++)
#pragma unroll
        for (int rr = 0; rr < 4; rr++) oc[nt][rr] = 0.f;

    uint32_t va = hb + (4 * TEN_H) + ((lane & 7) + ((lane >> 3) & 1) * 8) * 80
                  + ((lane >> 4) & 1) * 16;
#pragma unroll
    for (int ks = 0; ks < 4; ks++) {
        uint32_t ap[4];
        ap[0] = pack_h2(sc[2 * ks][0],     sc[2 * ks][1]);
        ap[1] = pack_h2(sc[2 * ks][2],     sc[2 * ks][3]);
        ap[2] = pack_h2(sc[2 * ks + 1][0], sc[2 * ks + 1][1]);
        ap[3] = pack_h2(sc[2 * ks + 1][2], sc[2 * ks + 1][3]);
        uint32_t bv[2][4];
        ldsm4t(bv[0], va + ks * 16 * 80);
        ldsm4t(bv[1], va + ks * 16 * 80 + 32);
#pragma unroll
        for (int nt = 0; nt < 4; nt++)
            mma_f16(oc[nt], ap, bv[nt >> 1][(nt & 1) * 2], bv[nt >> 1][(nt & 1) * 2 + 1]);
    }

    // ---- normalize + store half ----
    __half* op = g_att_h + (size_t)b * NTOK * CDIM + h * 32;
#pragma unroll
    for (int nt = 0; nt < 4; nt++) {
        int d = nt * 8 + (lane & 3) * 2;
        *(half2*)(op + (size_t)r * CDIM + d) =
            __floats2half2_rn(oc[nt][0] * inv0, oc[nt][1] * inv0);
        *(half2*)(op + (size_t)(r + 8) * CDIM + d) =
            __floats2half2_rn(oc[nt][2] * inv1, oc[nt][3] * inv1);
    }
}

// ---------------- launcher ----------------
extern "C" void kernel_launch(void* const* d_in, const int* in_sizes, int n_in,
                              void* d_out, int out_size) {
    const float* x         = (const float*)d_in[0];
    const float* mask      = (const float*)d_in[1];
    const float* qkv_w     = (const float*)d_in[2];
    const float* q_bias    = (const float*)d_in[3];
    const float* v_bias    = (const float*)d_in[4];
    const float* rpb_table = (const float*)d_in[5];
    const float* proj_w    = (const float*)d_in[6];
    const float* proj_b    = (const float*)d_in[7];
    const int*   rel_index = (const int*)d_in[8];
    float* out = (float*)d_out;

    void *p_xh, *p_qkvh, *p_atth, *p_wqkv, *p_wproj, *p_qkvb;
    cudaGetSymbolAddress(&p_xh,    g_x_h);
    cudaGetSymbolAddress(&p_qkvh,  g_qkv_h);
    cudaGetSymbolAddress(&p_atth,  g_att_h);
    cudaGetSymbolAddress(&p_wqkv,  g_wqkv_h);
    cudaGetSymbolAddress(&p_wproj, g_wproj_h);
    cudaGetSymbolAddress(&p_qkvb,  g_qkvb);

    cudaFuncSetAttribute(gemm_h<true>,  cudaFuncAttributeMaxDynamicSharedMemorySize, GEMM_SMEM);
    cudaFuncSetAttribute(gemm_h<false>, cudaFuncAttributeMaxDynamicSharedMemorySize, GEMM_SMEM);
    cudaFuncSetAttribute(attn_kernel,   cudaFuncAttributeMaxDynamicSharedMemorySize, ATTN_SMEM);

    // idx 0: rpb gather + qkv bias vector
    prep_rpb_bias<<<256, 256>>>(rpb_table, rel_index, q_bias, v_bias);
    // idx 1: fused cvt_x + cmb(half) + cvt_wqkv + cvt_wproj
    big_prep<<<XB + PB + WB + WB2, 256>>>(x, mask, qkv_w, proj_w);

    // idx 2: QKV GEMM -> g_qkv_h
    gemm_h<true><<<dim3(1536 / 128, MROWS / 128), 256, GEMM_SMEM>>>(
        (const __half*)p_xh, (const __half*)p_wqkv, (const float*)p_qkvb,
        p_qkvh, 3 * CDIM, CDIM);

    // idx 3 (ncu capture slot): fused window attention, 4 heads/CTA
    attn_kernel<<<dim3(HEADS / 4, BWIN), 512, ATTN_SMEM>>>();

    // idx 4: proj GEMM -> out (fp32)
    gemm_h<false><<<dim3(CDIM / 128, MROWS / 128), 256, GEMM_SMEM>>>(
        (const __half*)p_atth, (const __half*)p_wproj, proj_b,
        out, CDIM, CDIM);
}

// round 15
// speedup vs baseline: 1.6561x; 1.0599x over previous
#include <cuda_runtime.h>
#include <cuda_fp16.h>
#include <cstdint>

#define HEADS 16
#define CDIM  512
#define NTOK  64
#define BWIN  2048
#define NWIN  256
#define MROWS (BWIN * NTOK)        // 131072

// ---------------- static scratch ----------------
__device__ __half g_x_h[(size_t)MROWS * CDIM];          // x in half
__device__ __half g_qkv_h[(size_t)MROWS * 3 * CDIM];    // qkv in half
__device__ __half g_att_h[(size_t)MROWS * CDIM];        // attn out in half
__device__ __half g_wqkv_h[3 * CDIM * CDIM];
__device__ __half g_wproj_h[CDIM * CDIM];
__device__ float  g_rpb[HEADS * NTOK * NTOK];
__device__ __half g_cmb_h[(size_t)NWIN * HEADS * NTOK * NTOK];  // rpb+mask, half (32MB)
__device__ float  g_qkvb[3 * CDIM];

// ---------------- helpers ----------------
__device__ __forceinline__ uint32_t s2u(const void* p) {
    uint32_t a;
    asm("{ .reg .u64 t; cvta.to.shared.u64 t, %1; cvt.u32.u64 %0, t; }" : "=r"(a) : "l"(p));
    return a;
}
__device__ __forceinline__ void cpa16(uint32_t dst, const void* src) {
    asm volatile("cp.async.cg.shared.global [%0], [%1], 16;" :: "r"(dst), "l"(src) : "memory");
}
__device__ __forceinline__ void ldsm4(uint32_t r[4], uint32_t a) {
    asm volatile("ldmatrix.sync.aligned.m8n8.x4.shared.b16 {%0,%1,%2,%3}, [%4];"
                 : "=r"(r[0]), "=r"(r[1]), "=r"(r[2]), "=r"(r[3]) : "r"(a));
}
__device__ __forceinline__ void ldsm4t(uint32_t r[4], uint32_t a) {
    asm volatile("ldmatrix.sync.aligned.m8n8.x4.trans.shared.b16 {%0,%1,%2,%3}, [%4];"
                 : "=r"(r[0]), "=r"(r[1]), "=r"(r[2]), "=r"(r[3]) : "r"(a));
}
__device__ __forceinline__ void mma_f16(float c[4], const uint32_t a[4],
                                        uint32_t b0, uint32_t b1) {
    asm volatile(
        "mma.sync.aligned.m16n8k16.row.col.f32.f16.f16.f32 "
        "{%0,%1,%2,%3}, {%4,%5,%6,%7}, {%8,%9}, {%0,%1,%2,%3};"
        : "+f"(c[0]), "+f"(c[1]), "+f"(c[2]), "+f"(c[3])
        : "r"(a[0]), "r"(a[1]), "r"(a[2]), "r"(a[3]), "r"(b0), "r"(b1));
}
__device__ __forceinline__ uint32_t pack_h2(float a, float b) {
    half2 h = __floats2half2_rn(a, b);
    return *reinterpret_cast<uint32_t*>(&h);
}

// ---------------- prep: rpb gather + qkv bias (merged) ----------------
__global__ void prep_rpb_bias(const float* __restrict__ rpb_table,
                              const int*   __restrict__ rel_index,
                              const float* __restrict__ q_bias,
                              const float* __restrict__ v_bias) {
    int idx = blockIdx.x * 256 + threadIdx.x;   // grid 256 -> 65536
    int h  = idx >> 12;
    int nm = idx & 4095;
    g_rpb[idx] = rpb_table[rel_index[nm] * HEADS + h];
    if (idx < 3 * CDIM) {
        float v = 0.f;
        if (idx < CDIM)           v = q_bias[idx];
        else if (idx >= 2 * CDIM) v = v_bias[idx - 2 * CDIM];
        g_qkvb[idx] = v;
    }
}

// ---------------- big_prep: cvt x, cvt wqkv, cvt wproj ----------
#define XB   65536        // x cvt       (16777216 float4 / 256)
#define WB   768          // wqkv cvt    (196608 float4 / 256)
#define WB2  256          // wproj cvt   (65536 float4 / 256)
__global__ void big_prep(const float* __restrict__ x,
                         const float* __restrict__ qkv_w,
                         const float* __restrict__ proj_w) {
    int bid = blockIdx.x;
    if (bid < XB) {
        int i = bid * 256 + threadIdx.x;
        float4 v = ((const float4*)x)[i];
        ((half2*)g_x_h)[2 * i]     = __floats2half2_rn(v.x, v.y);
        ((half2*)g_x_h)[2 * i + 1] = __floats2half2_rn(v.z, v.w);
    } else if (bid < XB + WB) {
        int i = (bid - XB) * 256 + threadIdx.x;
        float4 v = ((const float4*)qkv_w)[i];
        ((half2*)g_wqkv_h)[2 * i]     = __floats2half2_rn(v.x, v.y);
        ((half2*)g_wqkv_h)[2 * i + 1] = __floats2half2_rn(v.z, v.w);
    } else {
        int i = (bid - XB - WB) * 256 + threadIdx.x;
        float4 v = ((const float4*)proj_w)[i];
        ((half2*)g_wproj_h)[2 * i]     = __floats2half2_rn(v.x, v.y);
        ((half2*)g_wproj_h)[2 * i + 1] = __floats2half2_rn(v.z, v.w);
    }
}

// ---------------- prep_cmb: cmb[w][h] = half(rpb[h] + mask[w]) ----------
__global__ void prep_cmb(const float* __restrict__ mask) {
    int i = blockIdx.x * 256 + threadIdx.x;      // float4 index (4194304 total)
    int nm4 = i & 1023;
    int wh  = i >> 10;
    int h = wh & (HEADS - 1), w = wh >> 4;
    float4 rb = ((const float4*)g_rpb)[(h << 10) + nm4];
    float4 mk = ((const float4*)mask)[((size_t)w << 10) + nm4];
    ((half2*)g_cmb_h)[2 * i]     = __floats2half2_rn(rb.x + mk.x, rb.y + mk.y);
    ((half2*)g_cmb_h)[2 * i + 1] = __floats2half2_rn(rb.z + mk.z, rb.w + mk.w);
}

// ---------------- fp16 GEMM (R6 8-warp): C = A*B^T + bias ----------------
#define BK      64
#define ROW_B   144
#define STG_A   (128 * ROW_B)
#define STG     (2 * STG_A)
#define NSTG    3
#define GEMM_SMEM (NSTG * STG)      // 110592
#define EROW    136                 // halves per epilogue-stage row

template<bool HOUT>
__global__ __launch_bounds__(256, 2)
void gemm_h(const __half* __restrict__ A, const __half* __restrict__ B,
            const float* __restrict__ bias, void* __restrict__ Cout,
            int N, int K) {
    extern __shared__ __align__(16) char smem[];
    const uint32_t sb = s2u(smem);
    const int tid = threadIdx.x, lane = tid & 31, warp = tid >> 5;
    const int wm = warp & 3, wn = warp >> 2;
    const int m0 = blockIdx.y * 128, n0 = blockIdx.x * 128;

    const __half* Ag = A + (size_t)m0 * K;
    const __half* Bg = B + (size_t)n0 * K;

    float c[2][8][4];
#pragma unroll
    for (int mt = 0; mt < 2; mt++)
#pragma unroll
        for (int nt = 0; nt < 8; nt++)
#pragma unroll
            for (int r = 0; r < 4; r++) c[mt][nt][r] = 0.f;

#define LOAD_STAGE(s, kb) do { \
    _Pragma("unroll") \
    for (int i = 0; i < 4; i++) { \
        int f = tid + 256 * i; \
        int row = f >> 3; int cc = f & 7; \
        cpa16(sb + (s) * STG + row * ROW_B + cc * 16, \
              Ag + (size_t)(kb) * BK + (size_t)row * K + cc * 8); \
        cpa16(sb + (s) * STG + STG_A + row * ROW_B + cc * 16, \
              Bg + (size_t)(kb) * BK + (size_t)row * K + cc * 8); \
    } \
    asm volatile("cp.async.commit_group;" ::: "memory"); \
} while (0)

    LOAD_STAGE(0, 0);
    LOAD_STAGE(1, 1);

    const uint32_t aoff = (wm * 32 + (lane & 15)) * ROW_B + (lane >> 4) * 16;
    const uint32_t boff = STG_A + (wn * 64 + (lane & 7) + ((lane >> 4) & 1) * 8) * ROW_B
                          + ((lane >> 3) & 1) * 16;
    const int KB = K / BK;   // 8

    for (int kb = 0; kb < KB; kb++) {
        if (kb + 2 < KB) asm volatile("cp.async.wait_group 1;" ::: "memory");
        else             asm volatile("cp.async.wait_group 0;" ::: "memory");
        __syncthreads();
        if (kb + 2 < KB) { int s = (kb + 2) % NSTG; LOAD_STAGE(s, kb + 2); }

        uint32_t ab = sb + (kb % NSTG) * STG + aoff;
        uint32_t bb = sb + (kb % NSTG) * STG + boff;
#pragma unroll
        for (int ks = 0; ks < 4; ks++) {
            uint32_t a[2][4], b[4][4];
#pragma unroll
            for (int mt = 0; mt < 2; mt++) ldsm4(a[mt], ab + mt * 16 * ROW_B + ks * 32);
#pragma unroll
            for (int jt = 0; jt < 4; jt++) ldsm4(b[jt], bb + jt * 16 * ROW_B + ks * 32);
#pragma unroll
            for (int mt = 0; mt < 2; mt++)
#pragma unroll
                for (int nt = 0; nt < 8; nt++)
                    mma_f16(c[mt][nt], a[mt], b[nt >> 1][(nt & 1) * 2], b[nt >> 1][(nt & 1) * 2 + 1]);
        }
    }

    if (HOUT) {
        // staged epilogue: biased half2 -> smem tile -> coalesced uint4 stores
        __syncthreads();
        __half* ep = (__half*)smem;
#pragma unroll
        for (int nt = 0; nt < 8; nt++) {
            int col = wn * 64 + nt * 8 + (lane & 3) * 2;
            float2 bv = *(const float2*)(bias + n0 + col);
#pragma unroll
            for (int mt = 0; mt < 2; mt++) {
                int r = wm * 32 + mt * 16 + (lane >> 2);
                *(half2*)(ep + r * EROW + col) =
                    __floats2half2_rn(c[mt][nt][0] + bv.x, c[mt][nt][1] + bv.y);
                *(half2*)(ep + (r + 8) * EROW + col) =
                    __floats2half2_rn(c[mt][nt][2] + bv.x, c[mt][nt][3] + bv.y);
            }
        }
        __syncthreads();
        __half* Cp = (__half*)Cout;
#pragma unroll
        for (int i = 0; i < 8; i++) {
            int idx = tid + 256 * i;            // 0..2047 = 128 rows x 16 chunks
            int row = idx >> 4, cc = idx & 15;
            *(uint4*)(Cp + (size_t)(m0 + row) * N + n0 + cc * 8) =
                *(const uint4*)(ep + row * EROW + cc * 8);
        }
    } else {
#pragma unroll
        for (int nt = 0; nt < 8; nt++) {
            int col = n0 + wn * 64 + nt * 8 + (lane & 3) * 2;
            float2 bv = *(const float2*)(bias + col);
            float* Cp = (float*)Cout;
#pragma unroll
            for (int mt = 0; mt < 2; mt++) {
                int r = m0 + wm * 32 + mt * 16 + (lane >> 2);
                *(float2*)(Cp + (size_t)r * N + col) =
                    make_float2(c[mt][nt][0] + bv.x, c[mt][nt][1] + bv.y);
                *(float2*)(Cp + (size_t)(r + 8) * N + col) =
                    make_float2(c[mt][nt][2] + bv.x, c[mt][nt][3] + bv.y);
            }
        }
    }
#undef LOAD_STAGE
}

// ---------------- fused window attention: 4 heads/CTA, staged cmb + O ------
#define HSTR_H 2592                     // halves per head block (5184B; mod128=64)
#define TEN_H  (4 * HSTR_H)             // halves per tensor block (q,k,v each)
#define CMB_OFF (3 * TEN_H)             // halves offset of cmb region
#define CMB_ROW 72                      // halves per cmb row (144B)
#define CMB_HEAD (64 * CMB_ROW)         // 4608 halves per head tile
#define ATTN_SMEM ((CMB_OFF + 4 * CMB_HEAD) * 2)   // 99072 B

__global__ __launch_bounds__(512, 2)
void attn_kernel() {
    extern __shared__ __align__(16) __half smh[];
    const int tid = threadIdx.x, lane = tid & 31, warp = tid >> 5;
    const int head = warp >> 2;                 // 0..3
    const int h = blockIdx.x * 4 + head;        // global head
    const int b = blockIdx.y, w = b & (NWIN - 1);

    // ---- cp.async stage of 4 cmb tiles (16B coalesced) ----
    {
        const __half* cmbg = g_cmb_h + ((size_t)(w * HEADS + blockIdx.x * 4) << 12);
        uint32_t cbase = s2u(smh) + CMB_OFF * 2;
#pragma unroll
        for (int i = 0; i < 4; i++) {
            int c   = tid + 512 * i;            // 0..2047
            int tl  = c >> 9;
            int rr  = (c >> 3) & 63;
            int cc  = c & 7;
            cpa16(cbase + (tl * CMB_HEAD + rr * CMB_ROW) * 2 + cc * 16,
                  cmbg + ((size_t)tl << 12) + rr * 64 + cc * 8);
        }
        asm volatile("cp.async.commit_group;" ::: "memory");
    }

    // ---- coalesced load of q,k,v for 4 heads ----
    {
        const __half* rowbase = g_qkv_h + (size_t)b * NTOK * 3 * CDIM + blockIdx.x * 128;
#pragma unroll
        for (int i = 0; i < 2; i++) {
            int c  = tid + 512 * i;             // 0..1023
            int rr = c >> 4, cc = c & 15;
            int hd = cc >> 2, hcol = (cc & 3) * 8;
            const __half* gp = rowbase + (size_t)rr * (3 * CDIM) + cc * 8;
            int dst = hd * HSTR_H + rr * 40 + hcol;
            *(uint4*)(smh + dst)             = *(const uint4*)(gp);
            *(uint4*)(smh + TEN_H + dst)     = *(const uint4*)(gp + CDIM);
            *(uint4*)(smh + 2 * TEN_H + dst) = *(const uint4*)(gp + 2 * CDIM);
        }
    }
    asm volatile("cp.async.wait_group 0;" ::: "memory");
    __syncthreads();

    const uint32_t hb = s2u(smh) + head * (HSTR_H * 2);
    const int rbase = (warp & 3) * 16;

    // ---- S = Q K^T ----
    float sc[8][4];
#pragma unroll
    for (int nt = 0; nt < 8; nt++)
#pragma unroll
        for (int r = 0; r < 4; r++) sc[nt][r] = 0.f;

    uint32_t qa = hb + (rbase + (lane & 15)) * 80 + (lane >> 4) * 16;
    uint32_t ka = hb + (TEN_H * 2) + ((lane & 7) + ((lane >> 4) & 1) * 8) * 80
                  + ((lane >> 3) & 1) * 16;
#pragma unroll
    for (int ks = 0; ks < 2; ks++) {
        uint32_t aq[4];
        ldsm4(aq, qa + ks * 32);
        uint32_t bk[4][4];
#pragma unroll
        for (int jt = 0; jt < 4; jt++) ldsm4(bk[jt], ka + jt * 16 * 80 + ks * 32);
#pragma unroll
        for (int nt = 0; nt < 8; nt++)
            mma_f16(sc[nt], aq, bk[nt >> 1][(nt & 1) * 2], bk[nt >> 1][(nt & 1) * 2 + 1]);
    }

    // ---- scale + cmb bias from smem ----
    const float scale = 0.17677669529663687f;   // 32^-0.5
    const int r = rbase + (lane >> 2);
    {
        const __half* cmbs = smh + CMB_OFF + head * CMB_HEAD;
#pragma unroll
        for (int nt = 0; nt < 8; nt++) {
            int col = nt * 8 + (lane & 3) * 2;
            float2 c0 = __half22float2(*(const half2*)(cmbs + r * CMB_ROW + col));
            sc[nt][0] = fmaf(sc[nt][0], scale, c0.x);
            sc[nt][1] = fmaf(sc[nt][1], scale, c0.y);
            float2 c1 = __half22float2(*(const half2*)(cmbs + (r + 8) * CMB_ROW + col));
            sc[nt][2] = fmaf(sc[nt][2], scale, c1.x);
            sc[nt][3] = fmaf(sc[nt][3], scale, c1.y);
        }
    }

    // ---- softmax in registers ----
    float mx0 = -1e30f, mx1 = -1e30f;
#pragma unroll
    for (int nt = 0; nt < 8; nt++) {
        mx0 = fmaxf(mx0, fmaxf(sc[nt][0], sc[nt][1]));
        mx1 = fmaxf(mx1, fmaxf(sc[nt][2], sc[nt][3]));
    }
    mx0 = fmaxf(mx0, __shfl_xor_sync(0xffffffff, mx0, 1));
    mx0 = fmaxf(mx0, __shfl_xor_sync(0xffffffff, mx0, 2));
    mx1 = fmaxf(mx1, __shfl_xor_sync(0xffffffff, mx1, 1));
    mx1 = fmaxf(mx1, __shfl_xor_sync(0xffffffff, mx1, 2));

    float s0 = 0.f, s1 = 0.f;
#pragma unroll
    for (int nt = 0; nt < 8; nt++) {
        sc[nt][0] = __expf(sc[nt][0] - mx0);
        sc[nt][1] = __expf(sc[nt][1] - mx0);
        s0 += sc[nt][0] + sc[nt][1];
        sc[nt][2] = __expf(sc[nt][2] - mx1);
        sc[nt][3] = __expf(sc[nt][3] - mx1);
        s1 += sc[nt][2] + sc[nt][3];
    }
    s0 += __shfl_xor_sync(0xffffffff, s0, 1);
    s0 += __shfl_xor_sync(0xffffffff, s0, 2);
    s1 += __shfl_xor_sync(0xffffffff, s1, 1);
    s1 += __shfl_xor_sync(0xffffffff, s1, 2);
    const float inv0 = 1.f / s0, inv1 = 1.f / s1;

    // ---- O = P V ----
    float oc[4][4];
#pragma unroll
    for (int nt = 0; nt < 4; nt++)
#pragma unroll
        for (int rr = 0; rr < 4; rr++) oc[nt][rr] = 0.f;

    uint32_t va = hb + (4 * TEN_H) + ((lane & 7) + ((lane >> 3) & 1) * 8) * 80
                  + ((lane >> 4) & 1) * 16;
#pragma unroll
    for (int ks = 0; ks < 4; ks++) {
        uint32_t ap[4];
        ap[0] = pack_h2(sc[2 * ks][0],     sc[2 * ks][1]);
        ap[1] = pack_h2(sc[2 * ks][2],     sc[2 * ks][3]);
        ap[2] = pack_h2(sc[2 * ks + 1][0], sc[2 * ks + 1][1]);
        ap[3] = pack_h2(sc[2 * ks + 1][2], sc[2 * ks + 1][3]);
        uint32_t bv[2][4];
        ldsm4t(bv[0], va + ks * 16 * 80);
        ldsm4t(bv[1], va + ks * 16 * 80 + 32);
#pragma unroll
        for (int nt = 0; nt < 4; nt++)
            mma_f16(oc[nt], ap, bv[nt >> 1][(nt & 1) * 2], bv[nt >> 1][(nt & 1) * 2 + 1]);
    }

    // ---- staged O store: normalize -> smem (cmb region) -> coalesced ----
    __syncthreads();                     // all cmb/v reads done; safe to reuse
    __half* eo = smh + CMB_OFF;          // 64 x 136 halves
#pragma unroll
    for (int nt = 0; nt < 4; nt++) {
        int d = head * 32 + nt * 8 + (lane & 3) * 2;
        *(half2*)(eo + r * EROW + d) =
            __floats2half2_rn(oc[nt][0] * inv0, oc[nt][1] * inv0);
        *(half2*)(eo + (r + 8) * EROW + d) =
            __floats2half2_rn(oc[nt][2] * inv1, oc[nt][3] * inv1);
    }
    __syncthreads();
    {
        __half* op = g_att_h + (size_t)b * NTOK * CDIM + blockIdx.x * 128;
#pragma unroll
        for (int i = 0; i < 2; i++) {
            int idx = tid + 512 * i;            // 0..1023 = 64 rows x 16 chunks
            int row = idx >> 4, cc = idx & 15;
            *(uint4*)(op + (size_t)row * CDIM + cc * 8) =
                *(const uint4*)(eo + row * EROW + cc * 8);
        }
    }
}

// ---------------- launcher ----------------
extern "C" void kernel_launch(void* const* d_in, const int* in_sizes, int n_in,
                              void* d_out, int out_size) {
    const float* x         = (const float*)d_in[0];
    const float* mask      = (const float*)d_in[1];
    const float* qkv_w     = (const float*)d_in[2];
    const float* q_bias    = (const float*)d_in[3];
    const float* v_bias    = (const float*)d_in[4];
    const float* rpb_table = (const float*)d_in[5];
    const float* proj_w    = (const float*)d_in[6];
    const float* proj_b    = (const float*)d_in[7];
    const int*   rel_index = (const int*)d_in[8];
    float* out = (float*)d_out;

    void *p_xh, *p_qkvh, *p_atth, *p_wqkv, *p_wproj, *p_qkvb;
    cudaGetSymbolAddress(&p_xh,    g_x_h);
    cudaGetSymbolAddress(&p_qkvh,  g_qkv_h);
    cudaGetSymbolAddress(&p_atth,  g_att_h);
    cudaGetSymbolAddress(&p_wqkv,  g_wqkv_h);
    cudaGetSymbolAddress(&p_wproj, g_wproj_h);
    cudaGetSymbolAddress(&p_qkvb,  g_qkvb);

    cudaFuncSetAttribute(gemm_h<true>,  cudaFuncAttributeMaxDynamicSharedMemorySize, GEMM_SMEM);
    cudaFuncSetAttribute(gemm_h<false>, cudaFuncAttributeMaxDynamicSharedMemorySize, GEMM_SMEM);
    cudaFuncSetAttribute(attn_kernel,   cudaFuncAttributeMaxDynamicSharedMemorySize, ATTN_SMEM);

    // idx 0: rpb gather + qkv bias vector
    prep_rpb_bias<<<256, 256>>>(rpb_table, rel_index, q_bias, v_bias);
    // idx 1: cvt x + wqkv + wproj
    big_prep<<<XB + WB + WB2, 256>>>(x, qkv_w, proj_w);
    // idx 2: cmb table (half)
    prep_cmb<<<16384, 256>>>(mask);

    // idx 3 (ncu capture slot): QKV GEMM with staged epilogue -> g_qkv_h
    gemm_h<true><<<dim3(1536 / 128, MROWS / 128), 256, GEMM_SMEM>>>(
        (const __half*)p_xh, (const __half*)p_wqkv, (const float*)p_qkvb,
        p_qkvh, 3 * CDIM, CDIM);

    // idx 4: fused window attention, 4 heads/CTA
    attn_kernel<<<dim3(HEADS / 4, BWIN), 512, ATTN_SMEM>>>();

    // idx 5: proj GEMM -> out (fp32)
    gemm_h<false><<<dim3(CDIM / 128, MROWS / 128), 256, GEMM_SMEM>>>(
        (const __half*)p_atth, (const __half*)p_wproj, proj_b,
        out, CDIM, CDIM);
}

// round 16
// speedup vs baseline: 1.8448x; 1.1139x over previous
#include <cuda_runtime.h>
#include <cuda_fp16.h>
#include <cstdint>

#define HEADS 16
#define CDIM  512
#define NTOK  64
#define BWIN  2048
#define NWIN  256
#define MROWS (BWIN * NTOK)        // 131072

// ---------------- static scratch ----------------
__device__ __half g_x_h[(size_t)MROWS * CDIM];          // x in half
__device__ __half g_qkv_h[(size_t)MROWS * 3 * CDIM];    // qkv in half
__device__ __half g_att_h[(size_t)MROWS * CDIM];        // attn out in half
__device__ __half g_wqkv_h[3 * CDIM * CDIM];
__device__ __half g_wproj_h[CDIM * CDIM];
__device__ float  g_rpb[HEADS * NTOK * NTOK];
__device__ __half g_cmb_h[(size_t)NWIN * HEADS * NTOK * NTOK];  // rpb+mask, half (32MB)
__device__ float  g_qkvb[3 * CDIM];

// ---------------- helpers ----------------
__device__ __forceinline__ uint32_t s2u(const void* p) {
    uint32_t a;
    asm("{ .reg .u64 t; cvta.to.shared.u64 t, %1; cvt.u32.u64 %0, t; }" : "=r"(a) : "l"(p));
    return a;
}
__device__ __forceinline__ void cpa16(uint32_t dst, const void* src) {
    asm volatile("cp.async.cg.shared.global [%0], [%1], 16;" :: "r"(dst), "l"(src) : "memory");
}
__device__ __forceinline__ void ldsm4(uint32_t r[4], uint32_t a) {
    asm volatile("ldmatrix.sync.aligned.m8n8.x4.shared.b16 {%0,%1,%2,%3}, [%4];"
                 : "=r"(r[0]), "=r"(r[1]), "=r"(r[2]), "=r"(r[3]) : "r"(a));
}
__device__ __forceinline__ void ldsm4t(uint32_t r[4], uint32_t a) {
    asm volatile("ldmatrix.sync.aligned.m8n8.x4.trans.shared.b16 {%0,%1,%2,%3}, [%4];"
                 : "=r"(r[0]), "=r"(r[1]), "=r"(r[2]), "=r"(r[3]) : "r"(a));
}
__device__ __forceinline__ void mma_f16(float c[4], const uint32_t a[4],
                                        uint32_t b0, uint32_t b1) {
    asm volatile(
        "mma.sync.aligned.m16n8k16.row.col.f32.f16.f16.f32 "
        "{%0,%1,%2,%3}, {%4,%5,%6,%7}, {%8,%9}, {%0,%1,%2,%3};"
        : "+f"(c[0]), "+f"(c[1]), "+f"(c[2]), "+f"(c[3])
        : "r"(a[0]), "r"(a[1]), "r"(a[2]), "r"(a[3]), "r"(b0), "r"(b1));
}
__device__ __forceinline__ uint32_t pack_h2(float a, float b) {
    half2 h = __floats2half2_rn(a, b);
    return *reinterpret_cast<uint32_t*>(&h);
}

// ---------------- prep: rpb gather + qkv bias (merged) ----------------
__global__ void prep_rpb_bias(const float* __restrict__ rpb_table,
                              const int*   __restrict__ rel_index,
                              const float* __restrict__ q_bias,
                              const float* __restrict__ v_bias) {
    int idx = blockIdx.x * 256 + threadIdx.x;   // grid 256 -> 65536
    int h  = idx >> 12;
    int nm = idx & 4095;
    g_rpb[idx] = rpb_table[rel_index[nm] * HEADS + h];
    if (idx < 3 * CDIM) {
        float v = 0.f;
        if (idx < CDIM)           v = q_bias[idx];
        else if (idx >= 2 * CDIM) v = v_bias[idx - 2 * CDIM];
        g_qkvb[idx] = v;
    }
}

// ---------------- big_prep: cvt x, cmb(half), cvt wqkv, cvt wproj ----------
// runs after prep_rpb_bias (same stream) so g_rpb is ready
#define XB   65536        // x cvt       (16777216 float4 / 256)
#define PB   16384        // cmb         (4194304 float4 / 256)
#define WB   768          // wqkv cvt    (196608 float4 / 256)
#define WB2  256          // wproj cvt   (65536 float4 / 256)
__global__ void big_prep(const float* __restrict__ x,
                         const float* __restrict__ mask,
                         const float* __restrict__ qkv_w,
                         const float* __restrict__ proj_w) {
    int bid = blockIdx.x;
    if (bid < XB) {
        int i = bid * 256 + threadIdx.x;
        float4 v = ((const float4*)x)[i];
        ((half2*)g_x_h)[2 * i]     = __floats2half2_rn(v.x, v.y);
        ((half2*)g_x_h)[2 * i + 1] = __floats2half2_rn(v.z, v.w);
    } else if (bid < XB + PB) {
        int i = (bid - XB) * 256 + threadIdx.x;
        int nm4 = i & 1023;
        int wh  = i >> 10;
        int h = wh & (HEADS - 1), w = wh >> 4;
        float4 rb = ((const float4*)g_rpb)[(h << 10) + nm4];
        float4 mk = ((const float4*)mask)[((size_t)w << 10) + nm4];
        ((half2*)g_cmb_h)[2 * i]     = __floats2half2_rn(rb.x + mk.x, rb.y + mk.y);
        ((half2*)g_cmb_h)[2 * i + 1] = __floats2half2_rn(rb.z + mk.z, rb.w + mk.w);
    } else if (bid < XB + PB + WB) {
        int i = (bid - XB - PB) * 256 + threadIdx.x;
        float4 v = ((const float4*)qkv_w)[i];
        ((half2*)g_wqkv_h)[2 * i]     = __floats2half2_rn(v.x, v.y);
        ((half2*)g_wqkv_h)[2 * i + 1] = __floats2half2_rn(v.z, v.w);
    } else {
        int i = (bid - XB - PB - WB) * 256 + threadIdx.x;
        float4 v = ((const float4*)proj_w)[i];
        ((half2*)g_wproj_h)[2 * i]     = __floats2half2_rn(v.x, v.y);
        ((half2*)g_wproj_h)[2 * i + 1] = __floats2half2_rn(v.z, v.w);
    }
}

// ---------------- fp16 GEMM (8-warp, compile-time K): C = A*B^T + bias ------
#define BK      64
#define ROW_B   144
#define STG_A   (128 * ROW_B)
#define STG     (2 * STG_A)
#define NSTG    3
#define GEMM_SMEM (NSTG * STG)      // 110592
#define EROW    136                 // halves per epilogue-stage row

template<bool HOUT, int K>
__global__ __launch_bounds__(256, 2)
void gemm_h(const __half* __restrict__ A, const __half* __restrict__ B,
            const float* __restrict__ bias, void* __restrict__ Cout,
            int N) {
    extern __shared__ __align__(16) char smem[];
    const uint32_t sb = s2u(smem);
    const int tid = threadIdx.x, lane = tid & 31, warp = tid >> 5;
    const int wm = warp & 3, wn = warp >> 2;
    const int m0 = blockIdx.y * 128, n0 = blockIdx.x * 128;

    const __half* Ag = A + (size_t)m0 * K;
    const __half* Bg = B + (size_t)n0 * K;

    float c[2][8][4];
#pragma unroll
    for (int mt = 0; mt < 2; mt++)
#pragma unroll
        for (int nt = 0; nt < 8; nt++)
#pragma unroll
            for (int r = 0; r < 4; r++) c[mt][nt][r] = 0.f;

#define LOAD_STAGE(s, kb) do { \
    _Pragma("unroll") \
    for (int i = 0; i < 4; i++) { \
        int f = tid + 256 * i; \
        int row = f >> 3; int cc = f & 7; \
        cpa16(sb + (s) * STG + row * ROW_B + cc * 16, \
              Ag + (size_t)(kb) * BK + (size_t)row * K + cc * 8); \
        cpa16(sb + (s) * STG + STG_A + row * ROW_B + cc * 16, \
              Bg + (size_t)(kb) * BK + (size_t)row * K + cc * 8); \
    } \
    asm volatile("cp.async.commit_group;" ::: "memory"); \
} while (0)

    LOAD_STAGE(0, 0);
    LOAD_STAGE(1, 1);

    const uint32_t aoff = (wm * 32 + (lane & 15)) * ROW_B + (lane >> 4) * 16;
    const uint32_t boff = STG_A + (wn * 64 + (lane & 7) + ((lane >> 4) & 1) * 8) * ROW_B
                          + ((lane >> 3) & 1) * 16;
    constexpr int KB = K / BK;   // 8 (compile-time)

#pragma unroll
    for (int kb = 0; kb < KB; kb++) {
        if (kb + 2 < KB) asm volatile("cp.async.wait_group 1;" ::: "memory");
        else             asm volatile("cp.async.wait_group 0;" ::: "memory");
        __syncthreads();
        if (kb + 2 < KB) LOAD_STAGE((kb + 2) % NSTG, kb + 2);

        uint32_t ab = sb + (kb % NSTG) * STG + aoff;
        uint32_t bb = sb + (kb % NSTG) * STG + boff;
#pragma unroll
        for (int ks = 0; ks < 4; ks++) {
            uint32_t a[2][4], b[4][4];
#pragma unroll
            for (int mt = 0; mt < 2; mt++) ldsm4(a[mt], ab + mt * 16 * ROW_B + ks * 32);
#pragma unroll
            for (int jt = 0; jt < 4; jt++) ldsm4(b[jt], bb + jt * 16 * ROW_B + ks * 32);
#pragma unroll
            for (int mt = 0; mt < 2; mt++)
#pragma unroll
                for (int nt = 0; nt < 8; nt++)
                    mma_f16(c[mt][nt], a[mt], b[nt >> 1][(nt & 1) * 2], b[nt >> 1][(nt & 1) * 2 + 1]);
        }
    }

    if (HOUT) {
        // staged epilogue: biased half2 -> smem tile -> coalesced uint4 stores
        __syncthreads();
        __half* ep = (__half*)smem;
#pragma unroll
        for (int nt = 0; nt < 8; nt++) {
            int col = wn * 64 + nt * 8 + (lane & 3) * 2;
            float2 bv = *(const float2*)(bias + n0 + col);
#pragma unroll
            for (int mt = 0; mt < 2; mt++) {
                int r = wm * 32 + mt * 16 + (lane >> 2);
                *(half2*)(ep + r * EROW + col) =
                    __floats2half2_rn(c[mt][nt][0] + bv.x, c[mt][nt][1] + bv.y);
                *(half2*)(ep + (r + 8) * EROW + col) =
                    __floats2half2_rn(c[mt][nt][2] + bv.x, c[mt][nt][3] + bv.y);
            }
        }
        __syncthreads();
        __half* Cp = (__half*)Cout;
#pragma unroll
        for (int i = 0; i < 8; i++) {
            int idx = tid + 256 * i;            // 0..2047 = 128 rows x 16 chunks
            int row = idx >> 4, cc = idx & 15;
            *(uint4*)(Cp + (size_t)(m0 + row) * N + n0 + cc * 8) =
                *(const uint4*)(ep + row * EROW + cc * 8);
        }
    } else {
#pragma unroll
        for (int nt = 0; nt < 8; nt++) {
            int col = n0 + wn * 64 + nt * 8 + (lane & 3) * 2;
            float2 bv = *(const float2*)(bias + col);
            float* Cp = (float*)Cout;
#pragma unroll
            for (int mt = 0; mt < 2; mt++) {
                int r = m0 + wm * 32 + mt * 16 + (lane >> 2);
                *(float2*)(Cp + (size_t)r * N + col) =
                    make_float2(c[mt][nt][0] + bv.x, c[mt][nt][1] + bv.y);
                *(float2*)(Cp + (size_t)(r + 8) * N + col) =
                    make_float2(c[mt][nt][2] + bv.x, c[mt][nt][3] + bv.y);
            }
        }
    }
#undef LOAD_STAGE
}

// ---------------- fused window attention: 4 heads/CTA, staged cmb + O ------
#define HSTR_H 2592                     // halves per head block (5184B; mod128=64)
#define TEN_H  (4 * HSTR_H)             // halves per tensor block (q,k,v each)
#define CMB_OFF (3 * TEN_H)             // halves offset of cmb region
#define CMB_ROW 72                      // halves per cmb row (144B)
#define CMB_HEAD (64 * CMB_ROW)         // 4608 halves per head tile
#define ATTN_SMEM ((CMB_OFF + 4 * CMB_HEAD) * 2)   // 99072 B

__global__ __launch_bounds__(512, 2)
void attn_kernel() {
    extern __shared__ __align__(16) __half smh[];
    const int tid = threadIdx.x, lane = tid & 31, warp = tid >> 5;
    const int head = warp >> 2;                 // 0..3
    const int h = blockIdx.x * 4 + head;        // global head
    const int b = blockIdx.y, w = b & (NWIN - 1);

    // ---- cp.async stage of 4 cmb tiles (16B coalesced) ----
    {
        const __half* cmbg = g_cmb_h + ((size_t)(w * HEADS + blockIdx.x * 4) << 12);
        uint32_t cbase = s2u(smh) + CMB_OFF * 2;
#pragma unroll
        for (int i = 0; i < 4; i++) {
            int c   = tid + 512 * i;            // 0..2047
            int tl  = c >> 9;
            int rr  = (c >> 3) & 63;
            int cc  = c & 7;
            cpa16(cbase + (tl * CMB_HEAD + rr * CMB_ROW) * 2 + cc * 16,
                  cmbg + ((size_t)tl << 12) + rr * 64 + cc * 8);
        }
        asm volatile("cp.async.commit_group;" ::: "memory");
    }

    // ---- coalesced load of q,k,v for 4 heads ----
    {
        const __half* rowbase = g_qkv_h + (size_t)b * NTOK * 3 * CDIM + blockIdx.x * 128;
#pragma unroll
        for (int i = 0; i < 2; i++) {
            int c  = tid + 512 * i;             // 0..1023
            int rr = c >> 4, cc = c & 15;
            int hd = cc >> 2, hcol = (cc & 3) * 8;
            const __half* gp = rowbase + (size_t)rr * (3 * CDIM) + cc * 8;
            int dst = hd * HSTR_H + rr * 40 + hcol;
            *(uint4*)(smh + dst)             = *(const uint4*)(gp);
            *(uint4*)(smh + TEN_H + dst)     = *(const uint4*)(gp + CDIM);
            *(uint4*)(smh + 2 * TEN_H + dst) = *(const uint4*)(gp + 2 * CDIM);
        }
    }
    asm volatile("cp.async.wait_group 0;" ::: "memory");
    __syncthreads();

    const uint32_t hb = s2u(smh) + head * (HSTR_H * 2);
    const int rbase = (warp & 3) * 16;

    // ---- S = Q K^T ----
    float sc[8][4];
#pragma unroll
    for (int nt = 0; nt < 8; nt++)
#pragma unroll
        for (int r = 0; r < 4; r++) sc[nt][r] = 0.f;

    uint32_t qa = hb + (rbase + (lane & 15)) * 80 + (lane >> 4) * 16;
    uint32_t ka = hb + (TEN_H * 2) + ((lane & 7) + ((lane >> 4) & 1) * 8) * 80
                  + ((lane >> 3) & 1) * 16;
#pragma unroll
    for (int ks = 0; ks < 2; ks++) {
        uint32_t aq[4];
        ldsm4(aq, qa + ks * 32);
        uint32_t bk[4][4];
#pragma unroll
        for (int jt = 0; jt < 4; jt++) ldsm4(bk[jt], ka + jt * 16 * 80 + ks * 32);
#pragma unroll
        for (int nt = 0; nt < 8; nt++)
            mma_f16(sc[nt], aq, bk[nt >> 1][(nt & 1) * 2], bk[nt >> 1][(nt & 1) * 2 + 1]);
    }

    // ---- scale + cmb bias from smem ----
    const float scale = 0.17677669529663687f;   // 32^-0.5
    const int r = rbase + (lane >> 2);
    {
        const __half* cmbs = smh + CMB_OFF + head * CMB_HEAD;
#pragma unroll
        for (int nt = 0; nt < 8; nt++) {
            int col = nt * 8 + (lane & 3) * 2;
            float2 c0 = __half22float2(*(const half2*)(cmbs + r * CMB_ROW + col));
            sc[nt][0] = fmaf(sc[nt][0], scale, c0.x);
            sc[nt][1] = fmaf(sc[nt][1], scale, c0.y);
            float2 c1 = __half22float2(*(const half2*)(cmbs + (r + 8) * CMB_ROW + col));
            sc[nt][2] = fmaf(sc[nt][2], scale, c1.x);
            sc[nt][3] = fmaf(sc[nt][3], scale, c1.y);
        }
    }

    // ---- softmax in registers ----
    float mx0 = -1e30f, mx1 = -1e30f;
#pragma unroll
    for (int nt = 0; nt < 8; nt++) {
        mx0 = fmaxf(mx0, fmaxf(sc[nt][0], sc[nt][1]));
        mx1 = fmaxf(mx1, fmaxf(sc[nt][2], sc[nt][3]));
    }
    mx0 = fmaxf(mx0, __shfl_xor_sync(0xffffffff, mx0, 1));
    mx0 = fmaxf(mx0, __shfl_xor_sync(0xffffffff, mx0, 2));
    mx1 = fmaxf(mx1, __shfl_xor_sync(0xffffffff, mx1, 1));
    mx1 = fmaxf(mx1, __shfl_xor_sync(0xffffffff, mx1, 2));

    float s0 = 0.f, s1 = 0.f;
#pragma unroll
    for (int nt = 0; nt < 8; nt++) {
        sc[nt][0] = __expf(sc[nt][0] - mx0);
        sc[nt][1] = __expf(sc[nt][1] - mx0);
        s0 += sc[nt][0] + sc[nt][1];
        sc[nt][2] = __expf(sc[nt][2] - mx1);
        sc[nt][3] = __expf(sc[nt][3] - mx1);
        s1 += sc[nt][2] + sc[nt][3];
    }
    s0 += __shfl_xor_sync(0xffffffff, s0, 1);
    s0 += __shfl_xor_sync(0xffffffff, s0, 2);
    s1 += __shfl_xor_sync(0xffffffff, s1, 1);
    s1 += __shfl_xor_sync(0xffffffff, s1, 2);
    const float inv0 = 1.f / s0, inv1 = 1.f / s1;

    // ---- O = P V ----
    float oc[4][4];
#pragma unroll
    for (int nt = 0; nt < 4; nt++)
#pragma unroll
        for (int rr = 0; rr < 4; rr++) oc[nt][rr] = 0.f;

    uint32_t va = hb + (4 * TEN_H) + ((lane & 7) + ((lane >> 3) & 1) * 8) * 80
                  + ((lane >> 4) & 1) * 16;
#pragma unroll
    for (int ks = 0; ks < 4; ks++) {
        uint32_t ap[4];
        ap[0] = pack_h2(sc[2 * ks][0],     sc[2 * ks][1]);
        ap[1] = pack_h2(sc[2 * ks][2],     sc[2 * ks][3]);
        ap[2] = pack_h2(sc[2 * ks + 1][0], sc[2 * ks + 1][1]);
        ap[3] = pack_h2(sc[2 * ks + 1][2], sc[2 * ks + 1][3]);
        uint32_t bv[2][4];
        ldsm4t(bv[0], va + ks * 16 * 80);
        ldsm4t(bv[1], va + ks * 16 * 80 + 32);
#pragma unroll
        for (int nt = 0; nt < 4; nt++)
            mma_f16(oc[nt], ap, bv[nt >> 1][(nt & 1) * 2], bv[nt >> 1][(nt & 1) * 2 + 1]);
    }

    // ---- staged O store: normalize -> smem (cmb region) -> coalesced ----
    __syncthreads();                     // all cmb/v reads done; safe to reuse
    __half* eo = smh + CMB_OFF;          // 64 x 136 halves
#pragma unroll
    for (int nt = 0; nt < 4; nt++) {
        int d = head * 32 + nt * 8 + (lane & 3) * 2;
        *(half2*)(eo + r * EROW + d) =
            __floats2half2_rn(oc[nt][0] * inv0, oc[nt][1] * inv0);
        *(half2*)(eo + (r + 8) * EROW + d) =
            __floats2half2_rn(oc[nt][2] * inv1, oc[nt][3] * inv1);
    }
    __syncthreads();
    {
        __half* op = g_att_h + (size_t)b * NTOK * CDIM + blockIdx.x * 128;
#pragma unroll
        for (int i = 0; i < 2; i++) {
            int idx = tid + 512 * i;            // 0..1023 = 64 rows x 16 chunks
            int row = idx >> 4, cc = idx & 15;
            *(uint4*)(op + (size_t)row * CDIM + cc * 8) =
                *(const uint4*)(eo + row * EROW + cc * 8);
        }
    }
}

// ---------------- launcher ----------------
extern "C" void kernel_launch(void* const* d_in, const int* in_sizes, int n_in,
                              void* d_out, int out_size) {
    const float* x         = (const float*)d_in[0];
    const float* mask      = (const float*)d_in[1];
    const float* qkv_w     = (const float*)d_in[2];
    const float* q_bias    = (const float*)d_in[3];
    const float* v_bias    = (const float*)d_in[4];
    const float* rpb_table = (const float*)d_in[5];
    const float* proj_w    = (const float*)d_in[6];
    const float* proj_b    = (const float*)d_in[7];
    const int*   rel_index = (const int*)d_in[8];
    float* out = (float*)d_out;

    void *p_xh, *p_qkvh, *p_atth, *p_wqkv, *p_wproj, *p_qkvb;
    cudaGetSymbolAddress(&p_xh,    g_x_h);
    cudaGetSymbolAddress(&p_qkvh,  g_qkv_h);
    cudaGetSymbolAddress(&p_atth,  g_att_h);
    cudaGetSymbolAddress(&p_wqkv,  g_wqkv_h);
    cudaGetSymbolAddress(&p_wproj, g_wproj_h);
    cudaGetSymbolAddress(&p_qkvb,  g_qkvb);

    cudaFuncSetAttribute((const void*)gemm_h<true, CDIM>,
                         cudaFuncAttributeMaxDynamicSharedMemorySize, GEMM_SMEM);
    cudaFuncSetAttribute((const void*)gemm_h<false, CDIM>,
                         cudaFuncAttributeMaxDynamicSharedMemorySize, GEMM_SMEM);
    cudaFuncSetAttribute(attn_kernel, cudaFuncAttributeMaxDynamicSharedMemorySize, ATTN_SMEM);

    // idx 0: rpb gather + qkv bias vector
    prep_rpb_bias<<<256, 256>>>(rpb_table, rel_index, q_bias, v_bias);
    // idx 1: cvt x + cmb(half) + wqkv + wproj (after rpb)
    big_prep<<<XB + PB + WB + WB2, 256>>>(x, mask, qkv_w, proj_w);

    // idx 2: QKV GEMM (compile-time K, unrolled) -> g_qkv_h
    gemm_h<true, CDIM><<<dim3(1536 / 128, MROWS / 128), 256, GEMM_SMEM>>>(
        (const __half*)p_xh, (const __half*)p_wqkv, (const float*)p_qkvb,
        p_qkvh, 3 * CDIM);

    // idx 3 (ncu capture slot): fused window attention, 4 heads/CTA
    attn_kernel<<<dim3(HEADS / 4, BWIN), 512, ATTN_SMEM>>>();

    // idx 4: proj GEMM -> out (fp32)
    gemm_h<false, CDIM><<<dim3(CDIM / 128, MROWS / 128), 256, GEMM_SMEM>>>(
        (const __half*)p_atth, (const __half*)p_wproj, proj_b,
        out, CDIM);
}